// round 9
// baseline (speedup 1.0000x reference)
#include <cuda_runtime.h>
#include <math.h>

#define BATCH 32

// scratch (device globals: sanctioned workaround for no-alloc rule)
__device__ float g_a1[32 * 64 * 126 * 126];
__device__ float g_p1[32 * 64 * 62 * 62];
__device__ float g_a2[32 * 64 * 60 * 60];
__device__ float g_p2[32 * 64 * 29 * 29];
__device__ float g_a3[32 * 64 * 27 * 27];
__device__ float g_p3[32 * 64 * 13 * 13];
__device__ double g_dsum[64];   // zero-init; re-zeroed after each consume
__device__ double g_dsq[64];
__device__ double g_xs[9];
__device__ float g_scale[4][64];
__device__ float g_bias[4][64];
__device__ float g_traw[32 * 6];
__device__ float g_theta[32 * 6];
__device__ int g_cnt0, g_cnt1, g_cnt2;   // last-block counters (self-reset)

// ---------------------------------------------------------------------------
// statsx: second moments of x; LAST BLOCK computes analytic BN0 scale/bias.
__global__ void statsx_kernel(const float* __restrict__ x,
                              const float* __restrict__ w0,
                              const float* __restrict__ gamma,
                              const float* __restrict__ beta) {
    __shared__ float red[256];
    __shared__ bool is_last;
    float a[9];
#pragma unroll
    for (int i = 0; i < 9; i++) a[i] = 0.f;
    for (int idx = blockIdx.x * 256 + threadIdx.x; idx < BATCH * 16384;
         idx += gridDim.x * 256) {
        int b = idx >> 14, p = idx & 16383;
        float x0 = x[(b * 3 + 0) * 16384 + p];
        float x1 = x[(b * 3 + 1) * 16384 + p];
        float x2 = x[(b * 3 + 2) * 16384 + p];
        a[0] = fmaf(x0, x0, a[0]); a[1] = fmaf(x0, x1, a[1]);
        a[2] = fmaf(x0, x2, a[2]); a[3] = fmaf(x1, x1, a[3]);
        a[4] = fmaf(x1, x2, a[4]); a[5] = fmaf(x2, x2, a[5]);
        a[6] += x0; a[7] += x1; a[8] += x2;
    }
#pragma unroll
    for (int q = 0; q < 9; q++) {
        red[threadIdx.x] = a[q];
        __syncthreads();
        for (int o = 128; o > 0; o >>= 1) {
            if (threadIdx.x < o) red[threadIdx.x] += red[threadIdx.x + o];
            __syncthreads();
        }
        if (threadIdx.x == 0) atomicAdd(&g_xs[q], (double)red[0]);
        __syncthreads();
    }
    // last-block: analytic BN0
    __threadfence();
    if (threadIdx.x == 0)
        is_last = (atomicAdd(&g_cnt0, 1) == (int)gridDim.x - 1);
    __syncthreads();
    if (!is_last) return;
    __threadfence();
    int o = threadIdx.x;
    if (o < 64) {
        const double N = 524288.0;
        double C00 = g_xs[0] / N, C01 = g_xs[1] / N, C02 = g_xs[2] / N;
        double C11 = g_xs[3] / N, C12 = g_xs[4] / N, C22 = g_xs[5] / N;
        double m0 = g_xs[6] / N, m1 = g_xs[7] / N, m2 = g_xs[8] / N;
        double w0v = w0[o * 3 + 0], w1v = w0[o * 3 + 1], w2v = w0[o * 3 + 2];
        double m = w0v * m0 + w1v * m1 + w2v * m2;
        double e2 = w0v * w0v * C00 + w1v * w1v * C11 + w2v * w2v * C22 +
                    2.0 * (w0v * w1v * C01 + w0v * w2v * C02 + w1v * w2v * C12);
        double var = e2 - m * m;
        double sc = (double)gamma[o] / sqrt(var + 1e-5);
        g_scale[0][o] = (float)sc;
        g_bias[0][o] = (float)((double)beta[o] - m * sc);
    }
    __syncthreads();
    if (threadIdx.x < 9) g_xs[threadIdx.x] = 0.0;
    if (threadIdx.x == 0) g_cnt0 = 0;
}

// ---------------------------------------------------------------------------
// conv inner: OCB out-channels x (2 rows x 4 cols) per thread, 9 taps
template <int OCB>
__device__ __forceinline__ void conv_tile_accum(const float* __restrict__ in_s,
                                                const float* __restrict__ ws,
                                                float acc[OCB][8], int cg,
                                                int ry, int cx) {
    float vin[4][6];
#pragma unroll
    for (int r = 0; r < 4; r++) {
        const float* ip = &in_s[(ry + r) * 20 + cx];
#pragma unroll
        for (int c = 0; c < 6; c++) vin[r][c] = ip[c];
    }
#pragma unroll
    for (int ch = 0; ch < OCB; ch++) {
        const float* wp = &ws[(cg * OCB + ch) * 12];
        float w[9];
#pragma unroll
        for (int t = 0; t < 9; t++) w[t] = wp[t];
#pragma unroll
        for (int r = 0; r < 2; r++) {
#pragma unroll
            for (int c = 0; c < 4; c++) {
                float s = acc[ch][r * 4 + c];
                s = fmaf(vin[r][c],     w[0], s);
                s = fmaf(vin[r][c + 1], w[1], s);
                s = fmaf(vin[r][c + 2], w[2], s);
                s = fmaf(vin[r + 1][c],     w[3], s);
                s = fmaf(vin[r + 1][c + 1], w[4], s);
                s = fmaf(vin[r + 1][c + 2], w[5], s);
                s = fmaf(vin[r + 2][c],     w[6], s);
                s = fmaf(vin[r + 2][c + 1], w[7], s);
                s = fmaf(vin[r + 2][c + 2], w[8], s);
                acc[ch][r * 4 + c] = s;
            }
        }
    }
}

// conv1: recompute conv0+bn0+relu per tile from x, then 3x3 conv (direct).
// Oct-buffered staging: one barrier per FOUR cins.
__global__ __launch_bounds__(256, 2) void conv1_kernel(
    const float* __restrict__ x, const float* __restrict__ w0,
    const float* __restrict__ w1) {
    __shared__ float xs[3][360];
    __shared__ float in_s[8][360];
    __shared__ float ws[8][64 * 12];
    const int b = blockIdx.y;
    const int tx = blockIdx.x & 7, ty = blockIdx.x >> 3;
    const int oy0 = ty * 16, ox0 = tx * 16;
    const int tid = threadIdx.x;
    const int cg = tid >> 5;
    const int sp = tid & 31;
    const int ry = (sp >> 2) * 2, cx = (sp & 3) * 4;

    float acc[8][8];
#pragma unroll
    for (int i = 0; i < 8; i++)
#pragma unroll
        for (int j = 0; j < 8; j++) acc[i][j] = 0.f;

    for (int idx = tid; idx < 3 * 324; idx += 256) {
        int c = idx / 324, p = idx - c * 324;
        int iy = p / 18, ix = p - iy * 18;
        int gy = oy0 + iy, gx = ox0 + ix;
        float v = 0.f;
        if (gy < 128 && gx < 128) v = x[((b * 3 + c) * 128 + gy) * 128 + gx];
        xs[c][iy * 20 + ix] = v;
    }
    __syncthreads();

    auto stage = [&](int cin, int bf) {
        float a0 = w0[cin * 3 + 0], a1 = w0[cin * 3 + 1], a2 = w0[cin * 3 + 2];
        float scl = g_scale[0][cin], bia = g_bias[0][cin];
        for (int idx = tid; idx < 324; idx += 256) {
            int iy = idx / 18, ix = idx - iy * 18;
            int o = iy * 20 + ix;
            float v = xs[0][o] * a0 + xs[1][o] * a1 + xs[2][o] * a2;
            in_s[bf][o] = fmaxf(fmaf(v, scl, bia), 0.f);
        }
        for (int idx = tid; idx < 576; idx += 256) {
            int o = idx / 9, t = idx - o * 9;
            ws[bf][o * 12 + t] = w1[(o * 64 + cin) * 9 + t];
        }
    };

    stage(0, 0); stage(1, 1); stage(2, 2); stage(3, 3);
    __syncthreads();
    for (int cin = 0; cin < 64; cin += 4) {
        if (cin + 4 < 64) {
            stage(cin + 4, (cin + 4) & 7);
            stage(cin + 5, (cin + 5) & 7);
            stage(cin + 6, (cin + 6) & 7);
            stage(cin + 7, (cin + 7) & 7);
        }
#pragma unroll
        for (int k = 0; k < 4; k++)
            conv_tile_accum<8>(in_s[(cin + k) & 7], ws[(cin + k) & 7], acc, cg,
                               ry, cx);
        __syncthreads();
    }

#pragma unroll
    for (int ch = 0; ch < 8; ch++) {
        const int och = cg * 8 + ch;
        float* db = g_a1 + ((size_t)(b * 64 + och)) * 126 * 126;
#pragma unroll
        for (int r = 0; r < 2; r++) {
            int oy = oy0 + ry + r;
            if (oy >= 126) continue;
#pragma unroll
            for (int c = 0; c < 4; c++) {
                int ox = ox0 + cx + c;
                if (ox < 126) db[oy * 126 + ox] = acc[ch][r * 4 + c];
            }
        }
    }
}

// generic 3x3 conv; OCB out-channels per thread, oc-split via blockIdx.z.
// Oct-buffered staging: one barrier per FOUR cins.
template <int IH, int OCB>
__global__ __launch_bounds__(256, 2) void conv3x3_kernel(
    const float* __restrict__ src, const float* __restrict__ wconv,
    float* __restrict__ dst, int lidx) {
    constexpr int OH = IH - 2;
    constexpr int TX = (OH + 15) / 16;
    constexpr int NOC = 8 * OCB;
    __shared__ float in_s[8][360];
    __shared__ float ws[8][NOC * 12];
    const int b = blockIdx.y;
    const int oc0 = blockIdx.z * NOC;
    const int tx = blockIdx.x % TX, ty = blockIdx.x / TX;
    const int oy0 = ty * 16, ox0 = tx * 16;
    const int tid = threadIdx.x;
    const int cg = tid >> 5;
    const int sp = tid & 31;
    const int ry = (sp >> 2) * 2, cx = (sp & 3) * 4;

    float acc[OCB][8];
#pragma unroll
    for (int i = 0; i < OCB; i++)
#pragma unroll
        for (int j = 0; j < 8; j++) acc[i][j] = 0.f;

    auto stage = [&](int cin, int bf) {
        float scl = g_scale[lidx][cin], bia = g_bias[lidx][cin];
        const float* sb = src + ((size_t)(b * 64 + cin)) * IH * IH;
        for (int idx = tid; idx < 324; idx += 256) {
            int iy = idx / 18, ix = idx - iy * 18;
            int gy = oy0 + iy, gx = ox0 + ix;
            float v = 0.f;
            if (gy < IH && gx < IH) v = sb[gy * IH + gx];
            in_s[bf][iy * 20 + ix] = fmaxf(fmaf(v, scl, bia), 0.f);
        }
        for (int idx = tid; idx < NOC * 9; idx += 256) {
            int o = idx / 9, t = idx - o * 9;
            ws[bf][o * 12 + t] = wconv[((oc0 + o) * 64 + cin) * 9 + t];
        }
    };

    stage(0, 0); stage(1, 1); stage(2, 2); stage(3, 3);
    __syncthreads();
    for (int cin = 0; cin < 64; cin += 4) {
        if (cin + 4 < 64) {
            stage(cin + 4, (cin + 4) & 7);
            stage(cin + 5, (cin + 5) & 7);
            stage(cin + 6, (cin + 6) & 7);
            stage(cin + 7, (cin + 7) & 7);
        }
#pragma unroll
        for (int k = 0; k < 4; k++)
            conv_tile_accum<OCB>(in_s[(cin + k) & 7], ws[(cin + k) & 7], acc,
                                 cg, ry, cx);
        __syncthreads();
    }

#pragma unroll
    for (int ch = 0; ch < OCB; ch++) {
        const int och = oc0 + cg * OCB + ch;
        float* db = dst + ((size_t)(b * 64 + och)) * OH * OH;
#pragma unroll
        for (int r = 0; r < 2; r++) {
            int oy = oy0 + ry + r;
            if (oy >= OH) continue;
#pragma unroll
            for (int c = 0; c < 4; c++) {
                int ox = ox0 + cx + c;
                if (ox < OH) db[oy * OH + ox] = acc[ch][r * 4 + c];
            }
        }
    }
}

// ---------------------------------------------------------------------------
// fused maxpool(3,2) + per-channel stats; LAST BLOCK computes scale/bias for
// layer l and re-zeroes accumulators.
template <int CH, int PH>
__global__ void poolstats_kernel(const float* __restrict__ src,
                                 float* __restrict__ dst, int l,
                                 const float* __restrict__ gamma,
                                 const float* __restrict__ beta, double N) {
    __shared__ float r1[256], r2[256];
    __shared__ bool is_last;
    int bc = blockIdx.x;
    int c = bc & 63;
    const float* sb = src + (size_t)bc * CH * CH;
    float* db = dst + (size_t)bc * PH * PH;
    float s = 0.f, q = 0.f;
    for (int i = threadIdx.x; i < PH * PH; i += 256) {
        int py = i / PH, px = i - py * PH;
        const float* w = sb + (2 * py) * CH + 2 * px;
        float m = w[0];
#pragma unroll
        for (int di = 0; di < 3; di++)
#pragma unroll
            for (int dj = 0; dj < 3; dj++) m = fmaxf(m, w[di * CH + dj]);
        db[i] = m;
        s += m;
        q = fmaf(m, m, q);
    }
    r1[threadIdx.x] = s; r2[threadIdx.x] = q;
    __syncthreads();
    for (int o = 128; o > 0; o >>= 1) {
        if (threadIdx.x < o) {
            r1[threadIdx.x] += r1[threadIdx.x + o];
            r2[threadIdx.x] += r2[threadIdx.x + o];
        }
        __syncthreads();
    }
    if (threadIdx.x == 0) {
        atomicAdd(&g_dsum[c], (double)r1[0]);
        atomicAdd(&g_dsq[c], (double)r2[0]);
    }
    // last-block: scale/bias
    __threadfence();
    if (threadIdx.x == 0)
        is_last = (atomicAdd(&g_cnt1, 1) == (int)gridDim.x - 1);
    __syncthreads();
    if (!is_last) return;
    __threadfence();
    int cc = threadIdx.x;
    if (cc < 64) {
        double m = g_dsum[cc] / N;
        double var = g_dsq[cc] / N - m * m;
        double sc = (double)gamma[cc] / sqrt(var + 1e-5);
        g_scale[l][cc] = (float)sc;
        g_bias[l][cc] = (float)((double)beta[cc] - m * sc);
    }
    __syncthreads();
    if (cc < 64) { g_dsum[cc] = 0.0; g_dsq[cc] = 0.0; }
    if (cc == 0) g_cnt1 = 0;
}

// ---------------------------------------------------------------------------
// FC; LAST BLOCK runs sequential spectral normalization.
__global__ void fc_kernel(const float* __restrict__ Wreg,
                          const float* __restrict__ breg,
                          const float* __restrict__ u0,
                          const float* __restrict__ v0) {
    __shared__ float red[256];
    __shared__ bool is_last;
    int j = blockIdx.x % 6, b = blockIdx.x / 6;
    const float* pb = g_p3 + (size_t)b * 10816;
    const float* wb = Wreg + (size_t)j * 10816;
    float s = 0.f;
    for (int k = threadIdx.x; k < 10816; k += 256) {
        int c = k / 169;
        float v = fmaxf(fmaf(pb[k], g_scale[3][c], g_bias[3][c]), 0.f);
        s += v * wb[k];
    }
    red[threadIdx.x] = s;
    __syncthreads();
    for (int o = 128; o > 0; o >>= 1) {
        if (threadIdx.x < o) red[threadIdx.x] += red[threadIdx.x + o];
        __syncthreads();
    }
    if (threadIdx.x == 0) g_traw[b * 6 + j] = red[0] + breg[j];
    // last-block: spectral norm
    __threadfence();
    if (threadIdx.x == 0)
        is_last = (atomicAdd(&g_cnt2, 1) == (int)gridDim.x - 1);
    __syncthreads();
    if (!is_last) return;
    if (threadIdx.x != 0) return;
    __threadfence();
    g_cnt2 = 0;
    float u[2] = {u0[0], u0[1]};
    float v[3] = {v0[0], v0[1], v0[2]};
    for (int bb = 0; bb < 32; bb++) {
        float W[6];
#pragma unroll
        for (int i = 0; i < 6; i++) W[i] = g_traw[bb * 6 + i];
#pragma unroll
        for (int it = 0; it < 4; it++) {
            float nv[3];
#pragma unroll
            for (int jj = 0; jj < 3; jj++)
                nv[jj] = W[jj] * u[0] + W[3 + jj] * u[1];
            float n = sqrtf(nv[0] * nv[0] + nv[1] * nv[1] + nv[2] * nv[2]);
            n = fmaxf(n, 1e-12f);
#pragma unroll
            for (int jj = 0; jj < 3; jj++) v[jj] = nv[jj] / n;
            float nu0 = W[0] * v[0] + W[1] * v[1] + W[2] * v[2];
            float nu1 = W[3] * v[0] + W[4] * v[1] + W[5] * v[2];
            n = sqrtf(nu0 * nu0 + nu1 * nu1);
            n = fmaxf(n, 1e-12f);
            u[0] = nu0 / n; u[1] = nu1 / n;
        }
        float Wv0 = W[0] * v[0] + W[1] * v[1] + W[2] * v[2];
        float Wv1 = W[3] * v[0] + W[4] * v[1] + W[5] * v[2];
        float sigma = u[0] * Wv0 + u[1] * Wv1;
#pragma unroll
        for (int i = 0; i < 6; i++) g_theta[bb * 6 + i] = W[i] / sigma;
    }
}

// affine grid + reflection bilinear sample
__global__ void sample_kernel(const float* __restrict__ x,
                              float* __restrict__ out) {
    int idx = blockIdx.x * 256 + threadIdx.x;
    if (idx >= BATCH * 16384) return;
    int b = idx >> 14, p = idx & 16383;
    int h = p >> 7, w = p & 127;
    const float* th = &g_theta[b * 6];
    float xsc = (2.f * w + 1.f) / 128.f - 1.f;
    float ysc = (2.f * h + 1.f) / 128.f - 1.f;
    float gx = th[0] * xsc + th[1] * ysc + th[2];
    float gy = th[3] * xsc + th[4] * ysc + th[5];
    float ix = ((gx + 1.f) * 128.f - 1.f) * 0.5f;
    float iy = ((gy + 1.f) * 128.f - 1.f) * 0.5f;
    float r = fmodf(fabsf(ix + 0.5f), 256.f);
    ix = (r > 128.f ? 256.f - r : r) - 0.5f;
    ix = fminf(fmaxf(ix, 0.f), 127.f);
    r = fmodf(fabsf(iy + 0.5f), 256.f);
    iy = (r > 128.f ? 256.f - r : r) - 0.5f;
    iy = fminf(fmaxf(iy, 0.f), 127.f);
    float fx0 = floorf(ix), fy0 = floorf(iy);
    float wx = ix - fx0, wy = iy - fy0;
    int x0 = min(max((int)fx0, 0), 127), y0 = min(max((int)fy0, 0), 127);
    int x1 = min(x0 + 1, 127), y1 = min(y0 + 1, 127);
    float w00 = (1.f - wx) * (1.f - wy), w10 = wx * (1.f - wy);
    float w01 = (1.f - wx) * wy, w11 = wx * wy;
#pragma unroll
    for (int c = 0; c < 3; c++) {
        const float* xb = x + (size_t)(b * 3 + c) * 16384;
        float v = xb[y0 * 128 + x0] * w00 + xb[y0 * 128 + x1] * w10 +
                  xb[y1 * 128 + x0] * w01 + xb[y1 * 128 + x1] * w11;
        out[(size_t)(b * 3 + c) * 16384 + p] = v;
    }
}

// ---------------------------------------------------------------------------
extern "C" void kernel_launch(void* const* d_in, const int* in_sizes, int n_in,
                              void* d_out, int out_size) {
    const float* x     = (const float*)d_in[0];
    const float* w0    = (const float*)d_in[1];
    const float* w1    = (const float*)d_in[2];
    const float* w2    = (const float*)d_in[3];
    const float* w3    = (const float*)d_in[4];
    const float* gamma = (const float*)d_in[5];
    const float* beta  = (const float*)d_in[6];
    const float* Wreg  = (const float*)d_in[7];
    const float* breg  = (const float*)d_in[8];
    const float* u0    = (const float*)d_in[9];
    const float* v0    = (const float*)d_in[10];
    float* out = (float*)d_out;
    (void)n_in; (void)in_sizes; (void)out_size;

    float *pa1, *pp1, *pa2, *pp2, *pa3, *pp3;
    cudaGetSymbolAddress((void**)&pa1, g_a1);
    cudaGetSymbolAddress((void**)&pp1, g_p1);
    cudaGetSymbolAddress((void**)&pa2, g_a2);
    cudaGetSymbolAddress((void**)&pp2, g_p2);
    cudaGetSymbolAddress((void**)&pa3, g_a3);
    cudaGetSymbolAddress((void**)&pp3, g_p3);

    // stats(x) + fused analytic BN0
    statsx_kernel<<<512, 256>>>(x, w0, gamma, beta);

    // conv1 (direct, fused conv0+bn0+relu) -> pool+stats+bn1
    conv1_kernel<<<dim3(64, 32), 256>>>(x, w0, w1);
    poolstats_kernel<126, 62>
        <<<2048, 256>>>(pa1, pp1, 1, gamma + 64, beta + 64, 123008.0);

    // conv2 (oc-split x4 to kill wave quantization) -> pool+stats+bn2
    conv3x3_kernel<62, 2><<<dim3(16, 32, 4), 256>>>(pp1, w2, pa2, 1);
    poolstats_kernel<60, 29>
        <<<2048, 256>>>(pa2, pp2, 2, gamma + 128, beta + 128, 26912.0);

    // conv3 (oc-split x2) -> pool+stats+bn3
    conv3x3_kernel<29, 4><<<dim3(4, 32, 2), 256>>>(pp2, w3, pa3, 2);
    poolstats_kernel<27, 13>
        <<<2048, 256>>>(pa3, pp3, 3, gamma + 192, beta + 192, 5408.0);

    // fc + fused spectral norm, then sampling
    fc_kernel<<<192, 256>>>(Wreg, breg, u0, v0);
    sample_kernel<<<(32 * 16384 + 255) / 256, 256>>>(x, out);
}

// round 10
// speedup vs baseline: 1.0539x; 1.0539x over previous
#include <cuda_runtime.h>
#include <math.h>

#define BATCH 32

// scratch (device globals: sanctioned workaround for no-alloc rule)
__device__ float g_a1[32 * 64 * 126 * 126];
__device__ float g_p1[32 * 64 * 62 * 62];
__device__ float g_a2[32 * 64 * 60 * 60];
__device__ float g_p2[32 * 64 * 29 * 29];
__device__ float g_a3[32 * 64 * 27 * 27];
__device__ float g_p3[32 * 64 * 13 * 13];
__device__ double g_dsum[64];   // zero-init; re-zeroed after each consume
__device__ double g_dsq[64];
__device__ double g_xs[9];
__device__ float g_scale[4][64];
__device__ float g_bias[4][64];
__device__ float g_traw[32 * 6];
__device__ float g_theta[32 * 6];
__device__ int g_cnt0, g_cnt1, g_cnt2;   // last-block counters (self-reset)

// ---------------------------------------------------------------------------
// statsx: second moments of x via warp shuffles; LAST BLOCK computes BN0.
__global__ void statsx_kernel(const float* __restrict__ x,
                              const float* __restrict__ w0,
                              const float* __restrict__ gamma,
                              const float* __restrict__ beta) {
    __shared__ float wred[8][9];
    __shared__ bool is_last;
    float a[9];
#pragma unroll
    for (int i = 0; i < 9; i++) a[i] = 0.f;
    for (int idx = blockIdx.x * 256 + threadIdx.x; idx < BATCH * 16384;
         idx += gridDim.x * 256) {
        int b = idx >> 14, p = idx & 16383;
        float x0 = x[(b * 3 + 0) * 16384 + p];
        float x1 = x[(b * 3 + 1) * 16384 + p];
        float x2 = x[(b * 3 + 2) * 16384 + p];
        a[0] = fmaf(x0, x0, a[0]); a[1] = fmaf(x0, x1, a[1]);
        a[2] = fmaf(x0, x2, a[2]); a[3] = fmaf(x1, x1, a[3]);
        a[4] = fmaf(x1, x2, a[4]); a[5] = fmaf(x2, x2, a[5]);
        a[6] += x0; a[7] += x1; a[8] += x2;
    }
    int lane = threadIdx.x & 31, wid = threadIdx.x >> 5;
#pragma unroll
    for (int q = 0; q < 9; q++) {
#pragma unroll
        for (int o = 16; o > 0; o >>= 1)
            a[q] += __shfl_xor_sync(0xffffffffu, a[q], o);
        if (lane == 0) wred[wid][q] = a[q];
    }
    __syncthreads();
    if (threadIdx.x < 9) {
        float s = 0.f;
#pragma unroll
        for (int w = 0; w < 8; w++) s += wred[w][threadIdx.x];
        atomicAdd(&g_xs[threadIdx.x], (double)s);
    }
    // last-block: analytic BN0
    __threadfence();
    if (threadIdx.x == 0)
        is_last = (atomicAdd(&g_cnt0, 1) == (int)gridDim.x - 1);
    __syncthreads();
    if (!is_last) return;
    __threadfence();
    int o = threadIdx.x;
    if (o < 64) {
        const double N = 524288.0;
        double C00 = g_xs[0] / N, C01 = g_xs[1] / N, C02 = g_xs[2] / N;
        double C11 = g_xs[3] / N, C12 = g_xs[4] / N, C22 = g_xs[5] / N;
        double m0 = g_xs[6] / N, m1 = g_xs[7] / N, m2 = g_xs[8] / N;
        double w0v = w0[o * 3 + 0], w1v = w0[o * 3 + 1], w2v = w0[o * 3 + 2];
        double m = w0v * m0 + w1v * m1 + w2v * m2;
        double e2 = w0v * w0v * C00 + w1v * w1v * C11 + w2v * w2v * C22 +
                    2.0 * (w0v * w1v * C01 + w0v * w2v * C02 + w1v * w2v * C12);
        double var = e2 - m * m;
        double sc = (double)gamma[o] / sqrt(var + 1e-5);
        g_scale[0][o] = (float)sc;
        g_bias[0][o] = (float)((double)beta[o] - m * sc);
    }
    __syncthreads();
    if (threadIdx.x < 9) g_xs[threadIdx.x] = 0.0;
    if (threadIdx.x == 0) g_cnt0 = 0;
}

// ---------------------------------------------------------------------------
// conv inner: OCB out-channels x (2 rows x 4 cols) per thread, 9 taps
template <int OCB>
__device__ __forceinline__ void conv_tile_accum(const float* __restrict__ in_s,
                                                const float* __restrict__ ws,
                                                float acc[OCB][8], int cg,
                                                int ry, int cx) {
    float vin[4][6];
#pragma unroll
    for (int r = 0; r < 4; r++) {
        const float* ip = &in_s[(ry + r) * 20 + cx];
#pragma unroll
        for (int c = 0; c < 6; c++) vin[r][c] = ip[c];
    }
#pragma unroll
    for (int ch = 0; ch < OCB; ch++) {
        const float* wp = &ws[(cg * OCB + ch) * 12];
        float w[9];
#pragma unroll
        for (int t = 0; t < 9; t++) w[t] = wp[t];
#pragma unroll
        for (int r = 0; r < 2; r++) {
#pragma unroll
            for (int c = 0; c < 4; c++) {
                float s = acc[ch][r * 4 + c];
                s = fmaf(vin[r][c],     w[0], s);
                s = fmaf(vin[r][c + 1], w[1], s);
                s = fmaf(vin[r][c + 2], w[2], s);
                s = fmaf(vin[r + 1][c],     w[3], s);
                s = fmaf(vin[r + 1][c + 1], w[4], s);
                s = fmaf(vin[r + 1][c + 2], w[5], s);
                s = fmaf(vin[r + 2][c],     w[6], s);
                s = fmaf(vin[r + 2][c + 1], w[7], s);
                s = fmaf(vin[r + 2][c + 2], w[8], s);
                acc[ch][r * 4 + c] = s;
            }
        }
    }
}

// conv1: recompute conv0+bn0+relu per tile from x, then 3x3 conv (direct).
// Quad-buffered staging: one barrier per TWO cins.
__global__ __launch_bounds__(256, 2) void conv1_kernel(
    const float* __restrict__ x, const float* __restrict__ w0,
    const float* __restrict__ w1) {
    __shared__ float xs[3][360];
    __shared__ float in_s[4][360];
    __shared__ float ws[4][64 * 12];
    const int b = blockIdx.y;
    const int tx = blockIdx.x & 7, ty = blockIdx.x >> 3;
    const int oy0 = ty * 16, ox0 = tx * 16;
    const int tid = threadIdx.x;
    const int cg = tid >> 5;
    const int sp = tid & 31;
    const int ry = (sp >> 2) * 2, cx = (sp & 3) * 4;

    float acc[8][8];
#pragma unroll
    for (int i = 0; i < 8; i++)
#pragma unroll
        for (int j = 0; j < 8; j++) acc[i][j] = 0.f;

    for (int idx = tid; idx < 3 * 324; idx += 256) {
        int c = idx / 324, p = idx - c * 324;
        int iy = p / 18, ix = p - iy * 18;
        int gy = oy0 + iy, gx = ox0 + ix;
        float v = 0.f;
        if (gy < 128 && gx < 128) v = x[((b * 3 + c) * 128 + gy) * 128 + gx];
        xs[c][iy * 20 + ix] = v;
    }
    __syncthreads();

    auto stage = [&](int cin, int bf) {
        float a0 = w0[cin * 3 + 0], a1 = w0[cin * 3 + 1], a2 = w0[cin * 3 + 2];
        float scl = g_scale[0][cin], bia = g_bias[0][cin];
        for (int idx = tid; idx < 324; idx += 256) {
            int iy = idx / 18, ix = idx - iy * 18;
            int o = iy * 20 + ix;
            float v = xs[0][o] * a0 + xs[1][o] * a1 + xs[2][o] * a2;
            in_s[bf][o] = fmaxf(fmaf(v, scl, bia), 0.f);
        }
        for (int idx = tid; idx < 576; idx += 256) {
            int o = idx / 9, t = idx - o * 9;
            ws[bf][o * 12 + t] = w1[(o * 64 + cin) * 9 + t];
        }
    };

    stage(0, 0);
    stage(1, 1);
    __syncthreads();
    for (int cin = 0; cin < 64; cin += 2) {
        if (cin + 2 < 64) {
            stage(cin + 2, (cin + 2) & 3);
            stage(cin + 3, (cin + 3) & 3);
        }
        conv_tile_accum<8>(in_s[cin & 3], ws[cin & 3], acc, cg, ry, cx);
        conv_tile_accum<8>(in_s[(cin + 1) & 3], ws[(cin + 1) & 3], acc, cg, ry,
                           cx);
        __syncthreads();
    }

#pragma unroll
    for (int ch = 0; ch < 8; ch++) {
        const int och = cg * 8 + ch;
        float* db = g_a1 + ((size_t)(b * 64 + och)) * 126 * 126;
#pragma unroll
        for (int r = 0; r < 2; r++) {
            int oy = oy0 + ry + r;
            if (oy >= 126) continue;
#pragma unroll
            for (int c = 0; c < 4; c++) {
                int ox = ox0 + cx + c;
                if (ox < 126) db[oy * 126 + ox] = acc[ch][r * 4 + c];
            }
        }
    }
}

// generic 3x3 conv; OCB out-channels per thread, oc-split via blockIdx.z.
// Quad-buffered staging: one barrier per TWO cins.
template <int IH, int OCB>
__global__ __launch_bounds__(256, 2) void conv3x3_kernel(
    const float* __restrict__ src, const float* __restrict__ wconv,
    float* __restrict__ dst, int lidx) {
    constexpr int OH = IH - 2;
    constexpr int TX = (OH + 15) / 16;
    constexpr int NOC = 8 * OCB;
    __shared__ float in_s[4][360];
    __shared__ float ws[4][NOC * 12];
    const int b = blockIdx.y;
    const int oc0 = blockIdx.z * NOC;
    const int tx = blockIdx.x % TX, ty = blockIdx.x / TX;
    const int oy0 = ty * 16, ox0 = tx * 16;
    const int tid = threadIdx.x;
    const int cg = tid >> 5;
    const int sp = tid & 31;
    const int ry = (sp >> 2) * 2, cx = (sp & 3) * 4;

    float acc[OCB][8];
#pragma unroll
    for (int i = 0; i < OCB; i++)
#pragma unroll
        for (int j = 0; j < 8; j++) acc[i][j] = 0.f;

    auto stage = [&](int cin, int bf) {
        float scl = g_scale[lidx][cin], bia = g_bias[lidx][cin];
        const float* sb = src + ((size_t)(b * 64 + cin)) * IH * IH;
        for (int idx = tid; idx < 324; idx += 256) {
            int iy = idx / 18, ix = idx - iy * 18;
            int gy = oy0 + iy, gx = ox0 + ix;
            float v = 0.f;
            if (gy < IH && gx < IH) v = sb[gy * IH + gx];
            in_s[bf][iy * 20 + ix] = fmaxf(fmaf(v, scl, bia), 0.f);
        }
        for (int idx = tid; idx < NOC * 9; idx += 256) {
            int o = idx / 9, t = idx - o * 9;
            ws[bf][o * 12 + t] = wconv[((oc0 + o) * 64 + cin) * 9 + t];
        }
    };

    stage(0, 0);
    stage(1, 1);
    __syncthreads();
    for (int cin = 0; cin < 64; cin += 2) {
        if (cin + 2 < 64) {
            stage(cin + 2, (cin + 2) & 3);
            stage(cin + 3, (cin + 3) & 3);
        }
        conv_tile_accum<OCB>(in_s[cin & 3], ws[cin & 3], acc, cg, ry, cx);
        conv_tile_accum<OCB>(in_s[(cin + 1) & 3], ws[(cin + 1) & 3], acc, cg,
                             ry, cx);
        __syncthreads();
    }

#pragma unroll
    for (int ch = 0; ch < OCB; ch++) {
        const int och = oc0 + cg * OCB + ch;
        float* db = dst + ((size_t)(b * 64 + och)) * OH * OH;
#pragma unroll
        for (int r = 0; r < 2; r++) {
            int oy = oy0 + ry + r;
            if (oy >= OH) continue;
#pragma unroll
            for (int c = 0; c < 4; c++) {
                int ox = ox0 + cx + c;
                if (ox < OH) db[oy * OH + ox] = acc[ch][r * 4 + c];
            }
        }
    }
}

// ---------------------------------------------------------------------------
// fused maxpool(3,2) + per-channel stats; LAST BLOCK computes scale/bias.
// PAIR=true: 2 horizontally-adjacent outputs per thread (even PH only).
template <int CH, int PH, bool PAIR>
__global__ void poolstats_kernel(const float* __restrict__ src,
                                 float* __restrict__ dst, int l,
                                 const float* __restrict__ gamma,
                                 const float* __restrict__ beta, double N) {
    __shared__ float r1[256], r2[256];
    __shared__ bool is_last;
    int bc = blockIdx.x;
    int c = bc & 63;
    const float* sb = src + (size_t)bc * CH * CH;
    float* db = dst + (size_t)bc * PH * PH;
    float s = 0.f, q = 0.f;
    if (PAIR) {
        constexpr int HP = PH / 2;
        for (int i = threadIdx.x; i < PH * HP; i += 256) {
            int py = i / HP, pxp = i - py * HP;
            const float* w = sb + (2 * py) * CH + 4 * pxp;
            float c0 = fmaxf(fmaxf(w[0], w[CH]), w[2 * CH]);
            float c1 = fmaxf(fmaxf(w[1], w[CH + 1]), w[2 * CH + 1]);
            float c2 = fmaxf(fmaxf(w[2], w[CH + 2]), w[2 * CH + 2]);
            float c3 = fmaxf(fmaxf(w[3], w[CH + 3]), w[2 * CH + 3]);
            float c4 = fmaxf(fmaxf(w[4], w[CH + 4]), w[2 * CH + 4]);
            float m0 = fmaxf(fmaxf(c0, c1), c2);
            float m1 = fmaxf(fmaxf(c2, c3), c4);
            db[py * PH + 2 * pxp] = m0;
            db[py * PH + 2 * pxp + 1] = m1;
            s += m0 + m1;
            q = fmaf(m0, m0, q);
            q = fmaf(m1, m1, q);
        }
    } else {
        for (int i = threadIdx.x; i < PH * PH; i += 256) {
            int py = i / PH, px = i - py * PH;
            const float* w = sb + (2 * py) * CH + 2 * px;
            float m = w[0];
#pragma unroll
            for (int di = 0; di < 3; di++)
#pragma unroll
                for (int dj = 0; dj < 3; dj++) m = fmaxf(m, w[di * CH + dj]);
            db[i] = m;
            s += m;
            q = fmaf(m, m, q);
        }
    }
    r1[threadIdx.x] = s; r2[threadIdx.x] = q;
    __syncthreads();
    for (int o = 128; o > 0; o >>= 1) {
        if (threadIdx.x < o) {
            r1[threadIdx.x] += r1[threadIdx.x + o];
            r2[threadIdx.x] += r2[threadIdx.x + o];
        }
        __syncthreads();
    }
    if (threadIdx.x == 0) {
        atomicAdd(&g_dsum[c], (double)r1[0]);
        atomicAdd(&g_dsq[c], (double)r2[0]);
    }
    // last-block: scale/bias
    __threadfence();
    if (threadIdx.x == 0)
        is_last = (atomicAdd(&g_cnt1, 1) == (int)gridDim.x - 1);
    __syncthreads();
    if (!is_last) return;
    __threadfence();
    int cc = threadIdx.x;
    if (cc < 64) {
        double m = g_dsum[cc] / N;
        double var = g_dsq[cc] / N - m * m;
        double sc = (double)gamma[cc] / sqrt(var + 1e-5);
        g_scale[l][cc] = (float)sc;
        g_bias[l][cc] = (float)((double)beta[cc] - m * sc);
    }
    __syncthreads();
    if (cc < 64) { g_dsum[cc] = 0.0; g_dsq[cc] = 0.0; }
    if (cc == 0) g_cnt1 = 0;
}

// ---------------------------------------------------------------------------
// FC; LAST BLOCK runs sequential spectral normalization.
__global__ void fc_kernel(const float* __restrict__ Wreg,
                          const float* __restrict__ breg,
                          const float* __restrict__ u0,
                          const float* __restrict__ v0) {
    __shared__ float red[256];
    __shared__ bool is_last;
    int j = blockIdx.x % 6, b = blockIdx.x / 6;
    const float* pb = g_p3 + (size_t)b * 10816;
    const float* wb = Wreg + (size_t)j * 10816;
    float s = 0.f;
    for (int k = threadIdx.x; k < 10816; k += 256) {
        int c = k / 169;
        float v = fmaxf(fmaf(pb[k], g_scale[3][c], g_bias[3][c]), 0.f);
        s += v * wb[k];
    }
    red[threadIdx.x] = s;
    __syncthreads();
    for (int o = 128; o > 0; o >>= 1) {
        if (threadIdx.x < o) red[threadIdx.x] += red[threadIdx.x + o];
        __syncthreads();
    }
    if (threadIdx.x == 0) g_traw[b * 6 + j] = red[0] + breg[j];
    // last-block: spectral norm
    __threadfence();
    if (threadIdx.x == 0)
        is_last = (atomicAdd(&g_cnt2, 1) == (int)gridDim.x - 1);
    __syncthreads();
    if (!is_last) return;
    if (threadIdx.x != 0) return;
    __threadfence();
    g_cnt2 = 0;
    float u[2] = {u0[0], u0[1]};
    float v[3] = {v0[0], v0[1], v0[2]};
    for (int bb = 0; bb < 32; bb++) {
        float W[6];
#pragma unroll
        for (int i = 0; i < 6; i++) W[i] = g_traw[bb * 6 + i];
#pragma unroll
        for (int it = 0; it < 4; it++) {
            float nv[3];
#pragma unroll
            for (int jj = 0; jj < 3; jj++)
                nv[jj] = W[jj] * u[0] + W[3 + jj] * u[1];
            float n = sqrtf(nv[0] * nv[0] + nv[1] * nv[1] + nv[2] * nv[2]);
            n = fmaxf(n, 1e-12f);
#pragma unroll
            for (int jj = 0; jj < 3; jj++) v[jj] = nv[jj] / n;
            float nu0 = W[0] * v[0] + W[1] * v[1] + W[2] * v[2];
            float nu1 = W[3] * v[0] + W[4] * v[1] + W[5] * v[2];
            n = sqrtf(nu0 * nu0 + nu1 * nu1);
            n = fmaxf(n, 1e-12f);
            u[0] = nu0 / n; u[1] = nu1 / n;
        }
        float Wv0 = W[0] * v[0] + W[1] * v[1] + W[2] * v[2];
        float Wv1 = W[3] * v[0] + W[4] * v[1] + W[5] * v[2];
        float sigma = u[0] * Wv0 + u[1] * Wv1;
#pragma unroll
        for (int i = 0; i < 6; i++) g_theta[bb * 6 + i] = W[i] / sigma;
    }
}

// affine grid + reflection bilinear sample
__global__ void sample_kernel(const float* __restrict__ x,
                              float* __restrict__ out) {
    int idx = blockIdx.x * 256 + threadIdx.x;
    if (idx >= BATCH * 16384) return;
    int b = idx >> 14, p = idx & 16383;
    int h = p >> 7, w = p & 127;
    const float* th = &g_theta[b * 6];
    float xsc = (2.f * w + 1.f) / 128.f - 1.f;
    float ysc = (2.f * h + 1.f) / 128.f - 1.f;
    float gx = th[0] * xsc + th[1] * ysc + th[2];
    float gy = th[3] * xsc + th[4] * ysc + th[5];
    float ix = ((gx + 1.f) * 128.f - 1.f) * 0.5f;
    float iy = ((gy + 1.f) * 128.f - 1.f) * 0.5f;
    float r = fmodf(fabsf(ix + 0.5f), 256.f);
    ix = (r > 128.f ? 256.f - r : r) - 0.5f;
    ix = fminf(fmaxf(ix, 0.f), 127.f);
    r = fmodf(fabsf(iy + 0.5f), 256.f);
    iy = (r > 128.f ? 256.f - r : r) - 0.5f;
    iy = fminf(fmaxf(iy, 0.f), 127.f);
    float fx0 = floorf(ix), fy0 = floorf(iy);
    float wx = ix - fx0, wy = iy - fy0;
    int x0 = min(max((int)fx0, 0), 127), y0 = min(max((int)fy0, 0), 127);
    int x1 = min(x0 + 1, 127), y1 = min(y0 + 1, 127);
    float w00 = (1.f - wx) * (1.f - wy), w10 = wx * (1.f - wy);
    float w01 = (1.f - wx) * wy, w11 = wx * wy;
#pragma unroll
    for (int c = 0; c < 3; c++) {
        const float* xb = x + (size_t)(b * 3 + c) * 16384;
        float v = xb[y0 * 128 + x0] * w00 + xb[y0 * 128 + x1] * w10 +
                  xb[y1 * 128 + x0] * w01 + xb[y1 * 128 + x1] * w11;
        out[(size_t)(b * 3 + c) * 16384 + p] = v;
    }
}

// ---------------------------------------------------------------------------
extern "C" void kernel_launch(void* const* d_in, const int* in_sizes, int n_in,
                              void* d_out, int out_size) {
    const float* x     = (const float*)d_in[0];
    const float* w0    = (const float*)d_in[1];
    const float* w1    = (const float*)d_in[2];
    const float* w2    = (const float*)d_in[3];
    const float* w3    = (const float*)d_in[4];
    const float* gamma = (const float*)d_in[5];
    const float* beta  = (const float*)d_in[6];
    const float* Wreg  = (const float*)d_in[7];
    const float* breg  = (const float*)d_in[8];
    const float* u0    = (const float*)d_in[9];
    const float* v0    = (const float*)d_in[10];
    float* out = (float*)d_out;
    (void)n_in; (void)in_sizes; (void)out_size;

    float *pa1, *pp1, *pa2, *pp2, *pa3, *pp3;
    cudaGetSymbolAddress((void**)&pa1, g_a1);
    cudaGetSymbolAddress((void**)&pp1, g_p1);
    cudaGetSymbolAddress((void**)&pa2, g_a2);
    cudaGetSymbolAddress((void**)&pp2, g_p2);
    cudaGetSymbolAddress((void**)&pa3, g_a3);
    cudaGetSymbolAddress((void**)&pp3, g_p3);

    // stats(x) + fused analytic BN0
    statsx_kernel<<<512, 256>>>(x, w0, gamma, beta);

    // conv1 (direct, fused conv0+bn0+relu) -> pool+stats+bn1
    conv1_kernel<<<dim3(64, 32), 256>>>(x, w0, w1);
    poolstats_kernel<126, 62, true>
        <<<2048, 256>>>(pa1, pp1, 1, gamma + 64, beta + 64, 123008.0);

    // conv2 -> pool+stats+bn2
    conv3x3_kernel<62, 8><<<dim3(16, 32, 1), 256>>>(pp1, w2, pa2, 1);
    poolstats_kernel<60, 29, false>
        <<<2048, 256>>>(pa2, pp2, 2, gamma + 128, beta + 128, 26912.0);

    // conv3 (oc-split x2) -> pool+stats+bn3
    conv3x3_kernel<29, 4><<<dim3(4, 32, 2), 256>>>(pp2, w3, pa3, 2);
    poolstats_kernel<27, 13, false>
        <<<2048, 256>>>(pa3, pp3, 3, gamma + 192, beta + 192, 5408.0);

    // fc + fused spectral norm, then sampling
    fc_kernel<<<192, 256>>>(Wreg, breg, u0, v0);
    sample_kernel<<<(32 * 16384 + 255) / 256, 256>>>(x, out);
}

// round 13
// speedup vs baseline: 1.3047x; 1.2380x over previous
#include <cuda_runtime.h>
#include <cuda_bf16.h>
#include <math.h>
#include <stdint.h>

#define BATCH 32

// scratch (device globals: sanctioned workaround for no-alloc rule)
__device__ float g_a1[32 * 64 * 126 * 126];
__device__ float g_p1[32 * 64 * 62 * 62];
__device__ float g_a2[32 * 64 * 60 * 60];
__device__ float g_p2[32 * 64 * 29 * 29];
__device__ float g_a3[32 * 64 * 27 * 27];
__device__ float g_p3[32 * 64 * 13 * 13];
__device__ __align__(16) char g_Bs[9][3][8192];  // pre-split swizzled w1 planes
__device__ double g_dsum[64];
__device__ double g_dsq[64];
__device__ double g_xs[9];
__device__ float g_scale[4][64];
__device__ float g_bias[4][64];
__device__ float g_traw[32 * 6];
__device__ float g_theta[32 * 6];
__device__ int g_cnt0, g_cnt1, g_cnt2;

// ---------------------------------------------------------------------------
__device__ __forceinline__ uint32_t smem_to_u32(const void* p) {
    uint32_t a;
    asm("{ .reg .u64 t; cvta.to.shared.u64 t, %1; cvt.u32.u64 %0, t; }"
        : "=r"(a) : "l"(p));
    return a;
}
#define SMEM_SWIZZLE_128B(bo) ((bo) ^ (((bo) >> 3) & 0x70))

__device__ __forceinline__ void ldsm_x4(uint32_t* r, uint32_t addr) {
    asm volatile(
        "ldmatrix.sync.aligned.m8n8.x4.shared.b16 {%0,%1,%2,%3}, [%4];"
        : "=r"(r[0]), "=r"(r[1]), "=r"(r[2]), "=r"(r[3]) : "r"(addr));
}
__device__ __forceinline__ void ldsm_x4t(uint32_t* r, uint32_t addr) {
    asm volatile(
        "ldmatrix.sync.aligned.m8n8.x4.trans.shared.b16 {%0,%1,%2,%3}, [%4];"
        : "=r"(r[0]), "=r"(r[1]), "=r"(r[2]), "=r"(r[3]) : "r"(addr));
}
__device__ __forceinline__ void mma_bf16(float* d, const uint32_t* a,
                                         const uint32_t* b) {
    asm volatile(
        "mma.sync.aligned.m16n8k16.row.col.f32.bf16.bf16.f32 "
        "{%0,%1,%2,%3}, {%4,%5,%6,%7}, {%8,%9}, {%0,%1,%2,%3};"
        : "+f"(d[0]), "+f"(d[1]), "+f"(d[2]), "+f"(d[3])
        : "r"(a[0]), "r"(a[1]), "r"(a[2]), "r"(a[3]), "r"(b[0]), "r"(b[1]));
}

// dynamic smem layout (bytes) for conv1_mma
#define C1_XS 0        // float[540]            (2160)
#define C1_H1 2176     // bf16 [180][64] SW128  (23040)
#define C1_H2 25216
#define C1_H3 48256
#define C1_B1 71296    // bf16 [64][64] SW128   (8192)
#define C1_B2 79488
#define C1_B3 87680
#define C1_SMEM 95872

// ---------------------------------------------------------------------------
// pre-split w1 into 3 bf16 planes per tap, stored SW128-swizzled [cin][cout]
__global__ void wsplit_kernel(const float* __restrict__ w1) {
    int s = blockIdx.x;
    for (int idx = threadIdx.x; idx < 4096; idx += 256) {
        int oc = idx >> 6, cin = idx & 63;
        float w = w1[(oc * 64 + cin) * 9 + s];
        __nv_bfloat16 w1b = __float2bfloat16(w);
        float r1 = w - __bfloat162float(w1b);
        __nv_bfloat16 w2b = __float2bfloat16(r1);
        __nv_bfloat16 w3b = __float2bfloat16(r1 - __bfloat162float(w2b));
        uint32_t off = SMEM_SWIZZLE_128B((uint32_t)(cin * 128 + oc * 2));
        *(__nv_bfloat16*)(&g_Bs[s][0][off]) = w1b;
        *(__nv_bfloat16*)(&g_Bs[s][1][off]) = w2b;
        *(__nv_bfloat16*)(&g_Bs[s][2][off]) = w3b;
    }
}

// ---------------------------------------------------------------------------
// statsx: second moments of x via warp shuffles; LAST BLOCK computes BN0.
__global__ void statsx_kernel(const float* __restrict__ x,
                              const float* __restrict__ w0,
                              const float* __restrict__ gamma,
                              const float* __restrict__ beta) {
    __shared__ float wred[8][9];
    __shared__ bool is_last;
    float a[9];
#pragma unroll
    for (int i = 0; i < 9; i++) a[i] = 0.f;
    for (int idx = blockIdx.x * 256 + threadIdx.x; idx < BATCH * 16384;
         idx += gridDim.x * 256) {
        int b = idx >> 14, p = idx & 16383;
        float x0 = x[(b * 3 + 0) * 16384 + p];
        float x1 = x[(b * 3 + 1) * 16384 + p];
        float x2 = x[(b * 3 + 2) * 16384 + p];
        a[0] = fmaf(x0, x0, a[0]); a[1] = fmaf(x0, x1, a[1]);
        a[2] = fmaf(x0, x2, a[2]); a[3] = fmaf(x1, x1, a[3]);
        a[4] = fmaf(x1, x2, a[4]); a[5] = fmaf(x2, x2, a[5]);
        a[6] += x0; a[7] += x1; a[8] += x2;
    }
    int lane = threadIdx.x & 31, wid = threadIdx.x >> 5;
#pragma unroll
    for (int q = 0; q < 9; q++) {
#pragma unroll
        for (int o = 16; o > 0; o >>= 1)
            a[q] += __shfl_xor_sync(0xffffffffu, a[q], o);
        if (lane == 0) wred[wid][q] = a[q];
    }
    __syncthreads();
    if (threadIdx.x < 9) {
        float s = 0.f;
#pragma unroll
        for (int w = 0; w < 8; w++) s += wred[w][threadIdx.x];
        atomicAdd(&g_xs[threadIdx.x], (double)s);
    }
    __threadfence();
    if (threadIdx.x == 0)
        is_last = (atomicAdd(&g_cnt0, 1) == (int)gridDim.x - 1);
    __syncthreads();
    if (!is_last) return;
    __threadfence();
    int o = threadIdx.x;
    if (o < 64) {
        const double N = 524288.0;
        double C00 = g_xs[0] / N, C01 = g_xs[1] / N, C02 = g_xs[2] / N;
        double C11 = g_xs[3] / N, C12 = g_xs[4] / N, C22 = g_xs[5] / N;
        double m0 = g_xs[6] / N, m1 = g_xs[7] / N, m2 = g_xs[8] / N;
        double w0v = w0[o * 3 + 0], w1v = w0[o * 3 + 1], w2v = w0[o * 3 + 2];
        double m = w0v * m0 + w1v * m1 + w2v * m2;
        double e2 = w0v * w0v * C00 + w1v * w1v * C11 + w2v * w2v * C22 +
                    2.0 * (w0v * w1v * C01 + w0v * w2v * C02 + w1v * w2v * C12);
        double var = e2 - m * m;
        double sc = (double)gamma[o] / sqrt(var + 1e-5);
        g_scale[0][o] = (float)sc;
        g_bias[0][o] = (float)((double)beta[o] - m * sc);
    }
    __syncthreads();
    if (threadIdx.x < 9) g_xs[threadIdx.x] = 0.0;
    if (threadIdx.x == 0) g_cnt0 = 0;
}

// ---------------------------------------------------------------------------
// conv1 via mma.sync, 3-way bf16 split (fp32-emulated GEMM), 9 taps.
// Block: 256 thr (8 warps), M=128 pixel rows (7x18 span), N=64 couts, K=64/tap.
__global__ __launch_bounds__(256, 2) void conv1_mma_kernel(
    const float* __restrict__ x, const float* __restrict__ w0,
    const float* __restrict__ w1) {
    extern __shared__ char smem[];
    float* xs = (float*)(smem + C1_XS);
    const uint32_t h1_b = smem_to_u32(smem + C1_H1);
    const uint32_t h2_b = smem_to_u32(smem + C1_H2);
    const uint32_t h3_b = smem_to_u32(smem + C1_H3);
    const uint32_t b1_b = smem_to_u32(smem + C1_B1);
    const uint32_t b2_b = smem_to_u32(smem + C1_B2);
    const uint32_t b3_b = smem_to_u32(smem + C1_B3);
    const int tid = threadIdx.x;
    const int lane = tid & 31, mw = tid >> 5;
    const int b = blockIdx.y;
    const int tx = blockIdx.x & 7, ty = blockIdx.x >> 3;
    const int y0 = ty * 7, x0 = tx * 16;

    for (int idx = tid; idx < 540; idx += 256) {
        int c = idx / 180, p = idx - c * 180;
        int ry = p / 20, rx = p - ry * 20;
        int gx = x0 + rx;
        float v = 0.f;
        if (gx < 128) v = x[((b * 3 + c) * 128 + (y0 + ry)) * 128 + gx];
        xs[c * 180 + p] = v;
    }
    __syncthreads();

    // h0 = relu(bn0(conv0(x))): 3-way bf16 split into [px][cin] SW128 layout
    {
        int j = lane;
        int c0 = 2 * j, c1 = 2 * j + 1;
        float a00 = w0[c0 * 3], a01 = w0[c0 * 3 + 1], a02 = w0[c0 * 3 + 2];
        float a10 = w0[c1 * 3], a11 = w0[c1 * 3 + 1], a12 = w0[c1 * 3 + 2];
        float s0 = g_scale[0][c0], bb0 = g_bias[0][c0];
        float s1 = g_scale[0][c1], bb1 = g_bias[0][c1];
        for (int p = mw; p < 180; p += 8) {
            float xv0 = xs[p], xv1 = xs[180 + p], xv2 = xs[360 + p];
            float v0 = fmaxf(fmaf(xv0 * a00 + xv1 * a01 + xv2 * a02, s0, bb0), 0.f);
            float v1 = fmaxf(fmaf(xv0 * a10 + xv1 * a11 + xv2 * a12, s1, bb1), 0.f);
            __nv_bfloat16 p0 = __float2bfloat16(v0);
            float r0 = v0 - __bfloat162float(p0);
            __nv_bfloat16 q0 = __float2bfloat16(r0);
            __nv_bfloat16 t0 = __float2bfloat16(r0 - __bfloat162float(q0));
            __nv_bfloat16 p1 = __float2bfloat16(v1);
            float r1 = v1 - __bfloat162float(p1);
            __nv_bfloat16 q1 = __float2bfloat16(r1);
            __nv_bfloat16 t1 = __float2bfloat16(r1 - __bfloat162float(q1));
            uint32_t off = SMEM_SWIZZLE_128B((uint32_t)(p * 128 + j * 4));
            *(uint32_t*)(smem + C1_H1 + off) =
                (uint32_t)__bfloat16_as_ushort(p0) |
                ((uint32_t)__bfloat16_as_ushort(p1) << 16);
            *(uint32_t*)(smem + C1_H2 + off) =
                (uint32_t)__bfloat16_as_ushort(q0) |
                ((uint32_t)__bfloat16_as_ushort(q1) << 16);
            *(uint32_t*)(smem + C1_H3 + off) =
                (uint32_t)__bfloat16_as_ushort(t0) |
                ((uint32_t)__bfloat16_as_ushort(t1) << 16);
        }
    }

    float acc[8][4];
#pragma unroll
    for (int j = 0; j < 8; j++)
#pragma unroll
        for (int q = 0; q < 4; q++) acc[j][q] = 0.f;

    for (int s = 0; s < 9; s++) {
        __syncthreads();  // h ready (s=0) / previous tap's ldmatrix done (s>0)
        // stage B planes: coalesced copies of pre-split, pre-swizzled weights
        for (int idx = tid; idx < 1536; idx += 256) {
            int pl = idx >> 9, q = idx & 511;
            ((uint4*)(smem + C1_B1 + pl * 8192))[q] =
                ((const uint4*)g_Bs[s][pl])[q];
        }
        __syncthreads();

        int ky = s / 3, kx = s - ky * 3;
        int m = mw * 16 + (lane & 15);
        int p = 0;
        if (m < 126) {
            int my = m / 18, mx = m - my * 18;
            p = (my + ky) * 20 + (mx + kx);
        }
        uint32_t arow = (uint32_t)(p * 128) + ((uint32_t)(lane >> 4) << 4);
#pragma unroll
        for (int kk = 0; kk < 4; kk++) {
            uint32_t a1[4], a2[4], a3[4];
            uint32_t ao = SMEM_SWIZZLE_128B(arow + kk * 32);
            ldsm_x4(a1, h1_b + ao);
            ldsm_x4(a2, h2_b + ao);
            ldsm_x4(a3, h3_b + ao);
            uint32_t brow = (uint32_t)((kk * 16 + (lane & 15)) * 128) +
                            ((uint32_t)(lane >> 4) << 4);
#pragma unroll
            for (int jp = 0; jp < 4; jp++) {
                uint32_t bb1[4], bb2[4], bb3[4];
                uint32_t bo = SMEM_SWIZZLE_128B(brow + jp * 32);
                ldsm_x4t(bb1, b1_b + bo);
                ldsm_x4t(bb2, b2_b + bo);
                ldsm_x4t(bb3, b3_b + bo);
                // j = 2*jp: fragments 0-1; j = 2*jp+1: fragments 2-3
                mma_bf16(acc[2 * jp], a1, bb1);
                mma_bf16(acc[2 * jp], a1, bb2);
                mma_bf16(acc[2 * jp], a2, bb1);
                mma_bf16(acc[2 * jp], a2, bb2);
                mma_bf16(acc[2 * jp], a1, bb3);
                mma_bf16(acc[2 * jp], a3, bb1);
                mma_bf16(acc[2 * jp + 1], a1, bb1 + 2);
                mma_bf16(acc[2 * jp + 1], a1, bb2 + 2);
                mma_bf16(acc[2 * jp + 1], a2, bb1 + 2);
                mma_bf16(acc[2 * jp + 1], a2, bb2 + 2);
                mma_bf16(acc[2 * jp + 1], a1, bb3 + 2);
                mma_bf16(acc[2 * jp + 1], a3, bb1 + 2);
            }
        }
    }

    // epilogue: transpose through smem for coalesced global stores
    __syncthreads();
    float* buf = (float*)smem;  // [128][65]
    int r0 = mw * 16 + (lane >> 2);
    int c0 = (lane & 3) * 2;
#pragma unroll
    for (int j = 0; j < 8; j++) {
        int oc = j * 8 + c0;
        buf[r0 * 65 + oc] = acc[j][0];
        buf[r0 * 65 + oc + 1] = acc[j][1];
        buf[(r0 + 8) * 65 + oc] = acc[j][2];
        buf[(r0 + 8) * 65 + oc + 1] = acc[j][3];
    }
    __syncthreads();
    for (int idx = tid; idx < 64 * 126; idx += 256) {
        int oc = idx / 126, m = idx - oc * 126;
        int my = m / 18, mx = m - my * 18;
        if (mx >= 16) continue;
        int ox = x0 + mx;
        if (ox >= 126) continue;
        g_a1[((size_t)(b * 64 + oc) * 126 + (y0 + my)) * 126 + ox] =
            buf[m * 65 + oc];
    }
}

// ---------------------------------------------------------------------------
// conv inner: OCB out-channels x (2 rows x 4 cols) per thread, 9 taps
template <int OCB>
__device__ __forceinline__ void conv_tile_accum(const float* __restrict__ in_s,
                                                const float* __restrict__ ws,
                                                float acc[OCB][8], int cg,
                                                int ry, int cx) {
    float vin[4][6];
#pragma unroll
    for (int r = 0; r < 4; r++) {
        const float* ip = &in_s[(ry + r) * 20 + cx];
#pragma unroll
        for (int c = 0; c < 6; c++) vin[r][c] = ip[c];
    }
#pragma unroll
    for (int ch = 0; ch < OCB; ch++) {
        const float* wp = &ws[(cg * OCB + ch) * 12];
        float w[9];
#pragma unroll
        for (int t = 0; t < 9; t++) w[t] = wp[t];
#pragma unroll
        for (int r = 0; r < 2; r++) {
#pragma unroll
            for (int c = 0; c < 4; c++) {
                float s = acc[ch][r * 4 + c];
                s = fmaf(vin[r][c],     w[0], s);
                s = fmaf(vin[r][c + 1], w[1], s);
                s = fmaf(vin[r][c + 2], w[2], s);
                s = fmaf(vin[r + 1][c],     w[3], s);
                s = fmaf(vin[r + 1][c + 1], w[4], s);
                s = fmaf(vin[r + 1][c + 2], w[5], s);
                s = fmaf(vin[r + 2][c],     w[6], s);
                s = fmaf(vin[r + 2][c + 1], w[7], s);
                s = fmaf(vin[r + 2][c + 2], w[8], s);
                acc[ch][r * 4 + c] = s;
            }
        }
    }
}

// generic 3x3 conv (direct); quad-buffered staging
template <int IH, int OCB>
__global__ __launch_bounds__(256, 2) void conv3x3_kernel(
    const float* __restrict__ src, const float* __restrict__ wconv,
    float* __restrict__ dst, int lidx) {
    constexpr int OH = IH - 2;
    constexpr int TX = (OH + 15) / 16;
    constexpr int NOC = 8 * OCB;
    __shared__ float in_s[4][360];
    __shared__ float ws[4][NOC * 12];
    const int b = blockIdx.y;
    const int oc0 = blockIdx.z * NOC;
    const int tx = blockIdx.x % TX, ty = blockIdx.x / TX;
    const int oy0 = ty * 16, ox0 = tx * 16;
    const int tid = threadIdx.x;
    const int cg = tid >> 5;
    const int sp = tid & 31;
    const int ry = (sp >> 2) * 2, cx = (sp & 3) * 4;

    float acc[OCB][8];
#pragma unroll
    for (int i = 0; i < OCB; i++)
#pragma unroll
        for (int j = 0; j < 8; j++) acc[i][j] = 0.f;

    auto stage = [&](int cin, int bf) {
        float scl = g_scale[lidx][cin], bia = g_bias[lidx][cin];
        const float* sb = src + ((size_t)(b * 64 + cin)) * IH * IH;
        for (int idx = tid; idx < 324; idx += 256) {
            int iy = idx / 18, ix = idx - iy * 18;
            int gy = oy0 + iy, gx = ox0 + ix;
            float v = 0.f;
            if (gy < IH && gx < IH) v = sb[gy * IH + gx];
            in_s[bf][iy * 20 + ix] = fmaxf(fmaf(v, scl, bia), 0.f);
        }
        for (int idx = tid; idx < NOC * 9; idx += 256) {
            int o = idx / 9, t = idx - o * 9;
            ws[bf][o * 12 + t] = wconv[((oc0 + o) * 64 + cin) * 9 + t];
        }
    };

    stage(0, 0);
    stage(1, 1);
    __syncthreads();
    for (int cin = 0; cin < 64; cin += 2) {
        if (cin + 2 < 64) {
            stage(cin + 2, (cin + 2) & 3);
            stage(cin + 3, (cin + 3) & 3);
        }
        conv_tile_accum<OCB>(in_s[cin & 3], ws[cin & 3], acc, cg, ry, cx);
        conv_tile_accum<OCB>(in_s[(cin + 1) & 3], ws[(cin + 1) & 3], acc, cg,
                             ry, cx);
        __syncthreads();
    }

#pragma unroll
    for (int ch = 0; ch < OCB; ch++) {
        const int och = oc0 + cg * OCB + ch;
        float* db = dst + ((size_t)(b * 64 + och)) * OH * OH;
#pragma unroll
        for (int r = 0; r < 2; r++) {
            int oy = oy0 + ry + r;
            if (oy >= OH) continue;
#pragma unroll
            for (int c = 0; c < 4; c++) {
                int ox = ox0 + cx + c;
                if (ox < OH) db[oy * OH + ox] = acc[ch][r * 4 + c];
            }
        }
    }
}

// ---------------------------------------------------------------------------
// fused maxpool(3,2) + per-channel stats; LAST BLOCK computes scale/bias.
template <int CH, int PH, bool PAIR>
__global__ void poolstats_kernel(const float* __restrict__ src,
                                 float* __restrict__ dst, int l,
                                 const float* __restrict__ gamma,
                                 const float* __restrict__ beta, double N) {
    __shared__ float r1[256], r2[256];
    __shared__ bool is_last;
    int bc = blockIdx.x;
    int c = bc & 63;
    const float* sb = src + (size_t)bc * CH * CH;
    float* db = dst + (size_t)bc * PH * PH;
    float s = 0.f, q = 0.f;
    if (PAIR) {
        constexpr int HP = PH / 2;
        for (int i = threadIdx.x; i < PH * HP; i += 256) {
            int py = i / HP, pxp = i - py * HP;
            const float* w = sb + (2 * py) * CH + 4 * pxp;
            float c0 = fmaxf(fmaxf(w[0], w[CH]), w[2 * CH]);
            float c1 = fmaxf(fmaxf(w[1], w[CH + 1]), w[2 * CH + 1]);
            float c2 = fmaxf(fmaxf(w[2], w[CH + 2]), w[2 * CH + 2]);
            float c3 = fmaxf(fmaxf(w[3], w[CH + 3]), w[2 * CH + 3]);
            float c4 = fmaxf(fmaxf(w[4], w[CH + 4]), w[2 * CH + 4]);
            float m0 = fmaxf(fmaxf(c0, c1), c2);
            float m1 = fmaxf(fmaxf(c2, c3), c4);
            db[py * PH + 2 * pxp] = m0;
            db[py * PH + 2 * pxp + 1] = m1;
            s += m0 + m1;
            q = fmaf(m0, m0, q);
            q = fmaf(m1, m1, q);
        }
    } else {
        for (int i = threadIdx.x; i < PH * PH; i += 256) {
            int py = i / PH, px = i - py * PH;
            const float* w = sb + (2 * py) * CH + 2 * px;
            float m = w[0];
#pragma unroll
            for (int di = 0; di < 3; di++)
#pragma unroll
                for (int dj = 0; dj < 3; dj++) m = fmaxf(m, w[di * CH + dj]);
            db[i] = m;
            s += m;
            q = fmaf(m, m, q);
        }
    }
    r1[threadIdx.x] = s; r2[threadIdx.x] = q;
    __syncthreads();
    for (int o = 128; o > 0; o >>= 1) {
        if (threadIdx.x < o) {
            r1[threadIdx.x] += r1[threadIdx.x + o];
            r2[threadIdx.x] += r2[threadIdx.x + o];
        }
        __syncthreads();
    }
    if (threadIdx.x == 0) {
        atomicAdd(&g_dsum[c], (double)r1[0]);
        atomicAdd(&g_dsq[c], (double)r2[0]);
    }
    __threadfence();
    if (threadIdx.x == 0)
        is_last = (atomicAdd(&g_cnt1, 1) == (int)gridDim.x - 1);
    __syncthreads();
    if (!is_last) return;
    __threadfence();
    int cc = threadIdx.x;
    if (cc < 64) {
        double m = g_dsum[cc] / N;
        double var = g_dsq[cc] / N - m * m;
        double sc = (double)gamma[cc] / sqrt(var + 1e-5);
        g_scale[l][cc] = (float)sc;
        g_bias[l][cc] = (float)((double)beta[cc] - m * sc);
    }
    __syncthreads();
    if (cc < 64) { g_dsum[cc] = 0.0; g_dsq[cc] = 0.0; }
    if (cc == 0) g_cnt1 = 0;
}

// ---------------------------------------------------------------------------
// FC; LAST BLOCK runs sequential spectral normalization.
__global__ void fc_kernel(const float* __restrict__ Wreg,
                          const float* __restrict__ breg,
                          const float* __restrict__ u0,
                          const float* __restrict__ v0) {
    __shared__ float red[256];
    __shared__ bool is_last;
    int j = blockIdx.x % 6, b = blockIdx.x / 6;
    const float* pb = g_p3 + (size_t)b * 10816;
    const float* wb = Wreg + (size_t)j * 10816;
    float s = 0.f;
    for (int k = threadIdx.x; k < 10816; k += 256) {
        int c = k / 169;
        float v = fmaxf(fmaf(pb[k], g_scale[3][c], g_bias[3][c]), 0.f);
        s += v * wb[k];
    }
    red[threadIdx.x] = s;
    __syncthreads();
    for (int o = 128; o > 0; o >>= 1) {
        if (threadIdx.x < o) red[threadIdx.x] += red[threadIdx.x + o];
        __syncthreads();
    }
    if (threadIdx.x == 0) g_traw[b * 6 + j] = red[0] + breg[j];
    __threadfence();
    if (threadIdx.x == 0)
        is_last = (atomicAdd(&g_cnt2, 1) == (int)gridDim.x - 1);
    __syncthreads();
    if (!is_last) return;
    if (threadIdx.x != 0) return;
    __threadfence();
    g_cnt2 = 0;
    float u[2] = {u0[0], u0[1]};
    float v[3] = {v0[0], v0[1], v0[2]};
    for (int bb = 0; bb < 32; bb++) {
        float W[6];
#pragma unroll
        for (int i = 0; i < 6; i++) W[i] = g_traw[bb * 6 + i];
#pragma unroll
        for (int it = 0; it < 4; it++) {
            float nv[3];
#pragma unroll
            for (int jj = 0; jj < 3; jj++)
                nv[jj] = W[jj] * u[0] + W[3 + jj] * u[1];
            float n = sqrtf(nv[0] * nv[0] + nv[1] * nv[1] + nv[2] * nv[2]);
            n = fmaxf(n, 1e-12f);
#pragma unroll
            for (int jj = 0; jj < 3; jj++) v[jj] = nv[jj] / n;
            float nu0 = W[0] * v[0] + W[1] * v[1] + W[2] * v[2];
            float nu1 = W[3] * v[0] + W[4] * v[1] + W[5] * v[2];
            n = sqrtf(nu0 * nu0 + nu1 * nu1);
            n = fmaxf(n, 1e-12f);
            u[0] = nu0 / n; u[1] = nu1 / n;
        }
        float Wv0 = W[0] * v[0] + W[1] * v[1] + W[2] * v[2];
        float Wv1 = W[3] * v[0] + W[4] * v[1] + W[5] * v[2];
        float sigma = u[0] * Wv0 + u[1] * Wv1;
#pragma unroll
        for (int i = 0; i < 6; i++) g_theta[bb * 6 + i] = W[i] / sigma;
    }
}

// affine grid + reflection bilinear sample
__global__ void sample_kernel(const float* __restrict__ x,
                              float* __restrict__ out) {
    int idx = blockIdx.x * 256 + threadIdx.x;
    if (idx >= BATCH * 16384) return;
    int b = idx >> 14, p = idx & 16383;
    int h = p >> 7, w = p & 127;
    const float* th = &g_theta[b * 6];
    float xsc = (2.f * w + 1.f) / 128.f - 1.f;
    float ysc = (2.f * h + 1.f) / 128.f - 1.f;
    float gx = th[0] * xsc + th[1] * ysc + th[2];
    float gy = th[3] * xsc + th[4] * ysc + th[5];
    float ix = ((gx + 1.f) * 128.f - 1.f) * 0.5f;
    float iy = ((gy + 1.f) * 128.f - 1.f) * 0.5f;
    float r = fmodf(fabsf(ix + 0.5f), 256.f);
    ix = (r > 128.f ? 256.f - r : r) - 0.5f;
    ix = fminf(fmaxf(ix, 0.f), 127.f);
    r = fmodf(fabsf(iy + 0.5f), 256.f);
    iy = (r > 128.f ? 256.f - r : r) - 0.5f;
    iy = fminf(fmaxf(iy, 0.f), 127.f);
    float fx0 = floorf(ix), fy0 = floorf(iy);
    float wx = ix - fx0, wy = iy - fy0;
    int x0 = min(max((int)fx0, 0), 127), y0 = min(max((int)fy0, 0), 127);
    int x1 = min(x0 + 1, 127), y1 = min(y0 + 1, 127);
    float w00 = (1.f - wx) * (1.f - wy), w10 = wx * (1.f - wy);
    float w01 = (1.f - wx) * wy, w11 = wx * wy;
#pragma unroll
    for (int c = 0; c < 3; c++) {
        const float* xb = x + (size_t)(b * 3 + c) * 16384;
        float v = xb[y0 * 128 + x0] * w00 + xb[y0 * 128 + x1] * w10 +
                  xb[y1 * 128 + x0] * w01 + xb[y1 * 128 + x1] * w11;
        out[(size_t)(b * 3 + c) * 16384 + p] = v;
    }
}

// ---------------------------------------------------------------------------
extern "C" void kernel_launch(void* const* d_in, const int* in_sizes, int n_in,
                              void* d_out, int out_size) {
    const float* x     = (const float*)d_in[0];
    const float* w0    = (const float*)d_in[1];
    const float* w1    = (const float*)d_in[2];
    const float* w2    = (const float*)d_in[3];
    const float* w3    = (const float*)d_in[4];
    const float* gamma = (const float*)d_in[5];
    const float* beta  = (const float*)d_in[6];
    const float* Wreg  = (const float*)d_in[7];
    const float* breg  = (const float*)d_in[8];
    const float* u0    = (const float*)d_in[9];
    const float* v0    = (const float*)d_in[10];
    float* out = (float*)d_out;
    (void)n_in; (void)in_sizes; (void)out_size;

    float *pa1, *pp1, *pa2, *pp2, *pa3, *pp3;
    cudaGetSymbolAddress((void**)&pa1, g_a1);
    cudaGetSymbolAddress((void**)&pp1, g_p1);
    cudaGetSymbolAddress((void**)&pa2, g_a2);
    cudaGetSymbolAddress((void**)&pp2, g_p2);
    cudaGetSymbolAddress((void**)&pa3, g_a3);
    cudaGetSymbolAddress((void**)&pp3, g_p3);

    cudaFuncSetAttribute(conv1_mma_kernel,
                         cudaFuncAttributeMaxDynamicSharedMemorySize, C1_SMEM);

    // weight pre-split + stats(x) + fused analytic BN0
    wsplit_kernel<<<9, 256>>>(w1);
    statsx_kernel<<<512, 256>>>(x, w0, gamma, beta);

    // conv1 (HMMA 3xBF16 implicit GEMM, fused conv0+bn0+relu) -> pool+stats+bn1
    conv1_mma_kernel<<<dim3(144, 32), 256, C1_SMEM>>>(x, w0, w1);
    poolstats_kernel<126, 62, true>
        <<<2048, 256>>>(pa1, pp1, 1, gamma + 64, beta + 64, 123008.0);

    // conv2 -> pool+stats+bn2
    conv3x3_kernel<62, 8><<<dim3(16, 32, 1), 256>>>(pp1, w2, pa2, 1);
    poolstats_kernel<60, 29, false>
        <<<2048, 256>>>(pa2, pp2, 2, gamma + 128, beta + 128, 26912.0);

    // conv3 (oc-split x2) -> pool+stats+bn3
    conv3x3_kernel<29, 4><<<dim3(4, 32, 2), 256>>>(pp2, w3, pa3, 2);
    poolstats_kernel<27, 13, false>
        <<<2048, 256>>>(pa3, pp3, 3, gamma + 192, beta + 192, 5408.0);

    // fc + fused spectral norm, then sampling
    fc_kernel<<<192, 256>>>(Wreg, breg, u0, v0);
    sample_kernel<<<(32 * 16384 + 255) / 256, 256>>>(x, out);
}

// round 14
// speedup vs baseline: 1.6498x; 1.2646x over previous
#include <cuda_runtime.h>
#include <cuda_fp16.h>
#include <math.h>
#include <stdint.h>

#define BATCH 32

// scratch (device globals: sanctioned workaround for no-alloc rule)
__device__ float g_a1[32 * 64 * 126 * 126];
__device__ float g_p1[32 * 64 * 62 * 62];
__device__ float g_a2[32 * 64 * 60 * 60];
__device__ float g_p2[32 * 64 * 29 * 29];
__device__ float g_a3[32 * 64 * 27 * 27];
__device__ float g_p3[32 * 64 * 13 * 13];
__device__ __align__(16) char g_Bs[9][2][8192];  // pre-split swizzled w1 planes
__device__ double g_dsum[64];
__device__ double g_dsq[64];
__device__ double g_xs[9];
__device__ float g_scale[4][64];
__device__ float g_bias[4][64];
__device__ float g_traw[32 * 6];
__device__ float g_theta[32 * 6];
__device__ int g_cnt0, g_cnt1, g_cnt2;

// ---------------------------------------------------------------------------
__device__ __forceinline__ uint32_t smem_to_u32(const void* p) {
    uint32_t a;
    asm("{ .reg .u64 t; cvta.to.shared.u64 t, %1; cvt.u32.u64 %0, t; }"
        : "=r"(a) : "l"(p));
    return a;
}
#define SMEM_SWIZZLE_128B(bo) ((bo) ^ (((bo) >> 3) & 0x70))

__device__ __forceinline__ void ldsm_x4(uint32_t* r, uint32_t addr) {
    asm volatile(
        "ldmatrix.sync.aligned.m8n8.x4.shared.b16 {%0,%1,%2,%3}, [%4];"
        : "=r"(r[0]), "=r"(r[1]), "=r"(r[2]), "=r"(r[3]) : "r"(addr));
}
__device__ __forceinline__ void ldsm_x4t(uint32_t* r, uint32_t addr) {
    asm volatile(
        "ldmatrix.sync.aligned.m8n8.x4.trans.shared.b16 {%0,%1,%2,%3}, [%4];"
        : "=r"(r[0]), "=r"(r[1]), "=r"(r[2]), "=r"(r[3]) : "r"(addr));
}
__device__ __forceinline__ void mma_f16(float* d, const uint32_t* a,
                                        const uint32_t* b) {
    asm volatile(
        "mma.sync.aligned.m16n8k16.row.col.f32.f16.f16.f32 "
        "{%0,%1,%2,%3}, {%4,%5,%6,%7}, {%8,%9}, {%0,%1,%2,%3};"
        : "+f"(d[0]), "+f"(d[1]), "+f"(d[2]), "+f"(d[3])
        : "r"(a[0]), "r"(a[1]), "r"(a[2]), "r"(a[3]), "r"(b[0]), "r"(b[1]));
}

// dynamic smem layout (bytes) for conv1_mma
#define C1_XS 0        // float[540]            (2160)
#define C1_H1 2176     // fp16 [180][64] SW128  (23040)
#define C1_H2 25216
#define C1_B1 48256    // fp16 [64][64] SW128   (8192)
#define C1_B2 56448
#define C1_SMEM 64640

// ---------------------------------------------------------------------------
// pre-split w1 into 2 fp16 planes per tap, stored SW128-swizzled [cin][cout]
__global__ void wsplit_kernel(const float* __restrict__ w1) {
    int s = blockIdx.x;
    for (int idx = threadIdx.x; idx < 4096; idx += 256) {
        int oc = idx >> 6, cin = idx & 63;
        float w = w1[(oc * 64 + cin) * 9 + s];
        __half w1h = __float2half(w);
        __half w2h = __float2half(w - __half2float(w1h));
        uint32_t off = SMEM_SWIZZLE_128B((uint32_t)(cin * 128 + oc * 2));
        *(__half*)(&g_Bs[s][0][off]) = w1h;
        *(__half*)(&g_Bs[s][1][off]) = w2h;
    }
}

// ---------------------------------------------------------------------------
// statsx: second moments of x via warp shuffles; LAST BLOCK computes BN0.
__global__ void statsx_kernel(const float* __restrict__ x,
                              const float* __restrict__ w0,
                              const float* __restrict__ gamma,
                              const float* __restrict__ beta) {
    __shared__ float wred[8][9];
    __shared__ bool is_last;
    float a[9];
#pragma unroll
    for (int i = 0; i < 9; i++) a[i] = 0.f;
    for (int idx = blockIdx.x * 256 + threadIdx.x; idx < BATCH * 16384;
         idx += gridDim.x * 256) {
        int b = idx >> 14, p = idx & 16383;
        float x0 = x[(b * 3 + 0) * 16384 + p];
        float x1 = x[(b * 3 + 1) * 16384 + p];
        float x2 = x[(b * 3 + 2) * 16384 + p];
        a[0] = fmaf(x0, x0, a[0]); a[1] = fmaf(x0, x1, a[1]);
        a[2] = fmaf(x0, x2, a[2]); a[3] = fmaf(x1, x1, a[3]);
        a[4] = fmaf(x1, x2, a[4]); a[5] = fmaf(x2, x2, a[5]);
        a[6] += x0; a[7] += x1; a[8] += x2;
    }
    int lane = threadIdx.x & 31, wid = threadIdx.x >> 5;
#pragma unroll
    for (int q = 0; q < 9; q++) {
#pragma unroll
        for (int o = 16; o > 0; o >>= 1)
            a[q] += __shfl_xor_sync(0xffffffffu, a[q], o);
        if (lane == 0) wred[wid][q] = a[q];
    }
    __syncthreads();
    if (threadIdx.x < 9) {
        float s = 0.f;
#pragma unroll
        for (int w = 0; w < 8; w++) s += wred[w][threadIdx.x];
        atomicAdd(&g_xs[threadIdx.x], (double)s);
    }
    __threadfence();
    if (threadIdx.x == 0)
        is_last = (atomicAdd(&g_cnt0, 1) == (int)gridDim.x - 1);
    __syncthreads();
    if (!is_last) return;
    __threadfence();
    int o = threadIdx.x;
    if (o < 64) {
        const double N = 524288.0;
        double C00 = g_xs[0] / N, C01 = g_xs[1] / N, C02 = g_xs[2] / N;
        double C11 = g_xs[3] / N, C12 = g_xs[4] / N, C22 = g_xs[5] / N;
        double m0 = g_xs[6] / N, m1 = g_xs[7] / N, m2 = g_xs[8] / N;
        double w0v = w0[o * 3 + 0], w1v = w0[o * 3 + 1], w2v = w0[o * 3 + 2];
        double m = w0v * m0 + w1v * m1 + w2v * m2;
        double e2 = w0v * w0v * C00 + w1v * w1v * C11 + w2v * w2v * C22 +
                    2.0 * (w0v * w1v * C01 + w0v * w2v * C02 + w1v * w2v * C12);
        double var = e2 - m * m;
        double sc = (double)gamma[o] / sqrt(var + 1e-5);
        g_scale[0][o] = (float)sc;
        g_bias[0][o] = (float)((double)beta[o] - m * sc);
    }
    __syncthreads();
    if (threadIdx.x < 9) g_xs[threadIdx.x] = 0.0;
    if (threadIdx.x == 0) g_cnt0 = 0;
}

// ---------------------------------------------------------------------------
// conv1 via mma.sync, 2-plane fp16 split (3 products), 9 taps.
// Block: 256 thr (8 warps), M=128 pixel rows (7x18 span), N=64 couts, K=64/tap.
__global__ __launch_bounds__(256, 2) void conv1_mma_kernel(
    const float* __restrict__ x, const float* __restrict__ w0,
    const float* __restrict__ w1) {
    extern __shared__ char smem[];
    float* xs = (float*)(smem + C1_XS);
    const uint32_t h1_b = smem_to_u32(smem + C1_H1);
    const uint32_t h2_b = smem_to_u32(smem + C1_H2);
    const uint32_t b1_b = smem_to_u32(smem + C1_B1);
    const uint32_t b2_b = smem_to_u32(smem + C1_B2);
    const int tid = threadIdx.x;
    const int lane = tid & 31, mw = tid >> 5;
    const int b = blockIdx.y;
    const int tx = blockIdx.x & 7, ty = blockIdx.x >> 3;
    const int y0 = ty * 7, x0 = tx * 16;

    for (int idx = tid; idx < 540; idx += 256) {
        int c = idx / 180, p = idx - c * 180;
        int ry = p / 20, rx = p - ry * 20;
        int gx = x0 + rx;
        float v = 0.f;
        if (gx < 128) v = x[((b * 3 + c) * 128 + (y0 + ry)) * 128 + gx];
        xs[c * 180 + p] = v;
    }
    __syncthreads();

    // h0 = relu(bn0(conv0(x))): fp16 2-plane split into [px][cin] SW128 layout
    {
        int j = lane;
        int c0 = 2 * j, c1 = 2 * j + 1;
        float a00 = w0[c0 * 3], a01 = w0[c0 * 3 + 1], a02 = w0[c0 * 3 + 2];
        float a10 = w0[c1 * 3], a11 = w0[c1 * 3 + 1], a12 = w0[c1 * 3 + 2];
        float s0 = g_scale[0][c0], bb0 = g_bias[0][c0];
        float s1 = g_scale[0][c1], bb1 = g_bias[0][c1];
        for (int p = mw; p < 180; p += 8) {
            float xv0 = xs[p], xv1 = xs[180 + p], xv2 = xs[360 + p];
            float v0 = fmaxf(fmaf(xv0 * a00 + xv1 * a01 + xv2 * a02, s0, bb0), 0.f);
            float v1 = fmaxf(fmaf(xv0 * a10 + xv1 * a11 + xv2 * a12, s1, bb1), 0.f);
            __half p0 = __float2half(v0);
            __half q0 = __float2half(v0 - __half2float(p0));
            __half p1 = __float2half(v1);
            __half q1 = __float2half(v1 - __half2float(p1));
            uint32_t off = SMEM_SWIZZLE_128B((uint32_t)(p * 128 + j * 4));
            *(uint32_t*)(smem + C1_H1 + off) =
                (uint32_t)__half_as_ushort(p0) |
                ((uint32_t)__half_as_ushort(p1) << 16);
            *(uint32_t*)(smem + C1_H2 + off) =
                (uint32_t)__half_as_ushort(q0) |
                ((uint32_t)__half_as_ushort(q1) << 16);
        }
    }

    float acc[8][4];
#pragma unroll
    for (int j = 0; j < 8; j++)
#pragma unroll
        for (int q = 0; q < 4; q++) acc[j][q] = 0.f;

    for (int s = 0; s < 9; s++) {
        __syncthreads();  // h ready (s=0) / previous tap's ldmatrix done (s>0)
        // stage B planes: coalesced copies of pre-split, pre-swizzled weights
        for (int idx = tid; idx < 1024; idx += 256) {
            int pl = idx >> 9, q = idx & 511;
            ((uint4*)(smem + C1_B1 + pl * 8192))[q] =
                ((const uint4*)g_Bs[s][pl])[q];
        }
        __syncthreads();

        int ky = s / 3, kx = s - ky * 3;
        int m = mw * 16 + (lane & 15);
        int p = 0;
        if (m < 126) {
            int my = m / 18, mx = m - my * 18;
            p = (my + ky) * 20 + (mx + kx);
        }
        uint32_t arow = (uint32_t)(p * 128) + ((uint32_t)(lane >> 4) << 4);
#pragma unroll
        for (int kk = 0; kk < 4; kk++) {
            uint32_t a1[4], a2[4];
            uint32_t ao = SMEM_SWIZZLE_128B(arow + kk * 32);
            ldsm_x4(a1, h1_b + ao);
            ldsm_x4(a2, h2_b + ao);
            uint32_t brow = (uint32_t)((kk * 16 + (lane & 15)) * 128) +
                            ((uint32_t)(lane >> 4) << 4);
#pragma unroll
            for (int jp = 0; jp < 4; jp++) {
                uint32_t bb1[4], bb2[4];
                uint32_t bo = SMEM_SWIZZLE_128B(brow + jp * 32);
                ldsm_x4t(bb1, b1_b + bo);
                ldsm_x4t(bb2, b2_b + bo);
                // j = 2*jp: fragments 0-1; j = 2*jp+1: fragments 2-3
                mma_f16(acc[2 * jp], a1, bb1);
                mma_f16(acc[2 * jp], a1, bb2);
                mma_f16(acc[2 * jp], a2, bb1);
                mma_f16(acc[2 * jp + 1], a1, bb1 + 2);
                mma_f16(acc[2 * jp + 1], a1, bb2 + 2);
                mma_f16(acc[2 * jp + 1], a2, bb1 + 2);
            }
        }
    }

    // epilogue: transpose through smem for coalesced global stores
    __syncthreads();
    float* buf = (float*)smem;  // [128][65]
    int r0 = mw * 16 + (lane >> 2);
    int c0 = (lane & 3) * 2;
#pragma unroll
    for (int j = 0; j < 8; j++) {
        int oc = j * 8 + c0;
        buf[r0 * 65 + oc] = acc[j][0];
        buf[r0 * 65 + oc + 1] = acc[j][1];
        buf[(r0 + 8) * 65 + oc] = acc[j][2];
        buf[(r0 + 8) * 65 + oc + 1] = acc[j][3];
    }
    __syncthreads();
    for (int idx = tid; idx < 64 * 126; idx += 256) {
        int oc = idx / 126, m = idx - oc * 126;
        int my = m / 18, mx = m - my * 18;
        if (mx >= 16) continue;
        int ox = x0 + mx;
        if (ox >= 126) continue;
        g_a1[((size_t)(b * 64 + oc) * 126 + (y0 + my)) * 126 + ox] =
            buf[m * 65 + oc];
    }
}

// ---------------------------------------------------------------------------
// conv inner: OCB out-channels x (2 rows x 4 cols) per thread, 9 taps
template <int OCB>
__device__ __forceinline__ void conv_tile_accum(const float* __restrict__ in_s,
                                                const float* __restrict__ ws,
                                                float acc[OCB][8], int cg,
                                                int ry, int cx) {
    float vin[4][6];
#pragma unroll
    for (int r = 0; r < 4; r++) {
        const float* ip = &in_s[(ry + r) * 20 + cx];
#pragma unroll
        for (int c = 0; c < 6; c++) vin[r][c] = ip[c];
    }
#pragma unroll
    for (int ch = 0; ch < OCB; ch++) {
        const float* wp = &ws[(cg * OCB + ch) * 12];
        float w[9];
#pragma unroll
        for (int t = 0; t < 9; t++) w[t] = wp[t];
#pragma unroll
        for (int r = 0; r < 2; r++) {
#pragma unroll
            for (int c = 0; c < 4; c++) {
                float s = acc[ch][r * 4 + c];
                s = fmaf(vin[r][c],     w[0], s);
                s = fmaf(vin[r][c + 1], w[1], s);
                s = fmaf(vin[r][c + 2], w[2], s);
                s = fmaf(vin[r + 1][c],     w[3], s);
                s = fmaf(vin[r + 1][c + 1], w[4], s);
                s = fmaf(vin[r + 1][c + 2], w[5], s);
                s = fmaf(vin[r + 2][c],     w[6], s);
                s = fmaf(vin[r + 2][c + 1], w[7], s);
                s = fmaf(vin[r + 2][c + 2], w[8], s);
                acc[ch][r * 4 + c] = s;
            }
        }
    }
}

// generic 3x3 conv (direct); quad-buffered staging
template <int IH, int OCB>
__global__ __launch_bounds__(256, 2) void conv3x3_kernel(
    const float* __restrict__ src, const float* __restrict__ wconv,
    float* __restrict__ dst, int lidx) {
    constexpr int OH = IH - 2;
    constexpr int TX = (OH + 15) / 16;
    constexpr int NOC = 8 * OCB;
    __shared__ float in_s[4][360];
    __shared__ float ws[4][NOC * 12];
    const int b = blockIdx.y;
    const int oc0 = blockIdx.z * NOC;
    const int tx = blockIdx.x % TX, ty = blockIdx.x / TX;
    const int oy0 = ty * 16, ox0 = tx * 16;
    const int tid = threadIdx.x;
    const int cg = tid >> 5;
    const int sp = tid & 31;
    const int ry = (sp >> 2) * 2, cx = (sp & 3) * 4;

    float acc[OCB][8];
#pragma unroll
    for (int i = 0; i < OCB; i++)
#pragma unroll
        for (int j = 0; j < 8; j++) acc[i][j] = 0.f;

    auto stage = [&](int cin, int bf) {
        float scl = g_scale[lidx][cin], bia = g_bias[lidx][cin];
        const float* sb = src + ((size_t)(b * 64 + cin)) * IH * IH;
        for (int idx = tid; idx < 324; idx += 256) {
            int iy = idx / 18, ix = idx - iy * 18;
            int gy = oy0 + iy, gx = ox0 + ix;
            float v = 0.f;
            if (gy < IH && gx < IH) v = sb[gy * IH + gx];
            in_s[bf][iy * 20 + ix] = fmaxf(fmaf(v, scl, bia), 0.f);
        }
        for (int idx = tid; idx < NOC * 9; idx += 256) {
            int o = idx / 9, t = idx - o * 9;
            ws[bf][o * 12 + t] = wconv[((oc0 + o) * 64 + cin) * 9 + t];
        }
    };

    stage(0, 0);
    stage(1, 1);
    __syncthreads();
    for (int cin = 0; cin < 64; cin += 2) {
        if (cin + 2 < 64) {
            stage(cin + 2, (cin + 2) & 3);
            stage(cin + 3, (cin + 3) & 3);
        }
        conv_tile_accum<OCB>(in_s[cin & 3], ws[cin & 3], acc, cg, ry, cx);
        conv_tile_accum<OCB>(in_s[(cin + 1) & 3], ws[(cin + 1) & 3], acc, cg,
                             ry, cx);
        __syncthreads();
    }

#pragma unroll
    for (int ch = 0; ch < OCB; ch++) {
        const int och = oc0 + cg * OCB + ch;
        float* db = dst + ((size_t)(b * 64 + och)) * OH * OH;
#pragma unroll
        for (int r = 0; r < 2; r++) {
            int oy = oy0 + ry + r;
            if (oy >= OH) continue;
#pragma unroll
            for (int c = 0; c < 4; c++) {
                int ox = ox0 + cx + c;
                if (ox < OH) db[oy * OH + ox] = acc[ch][r * 4 + c];
            }
        }
    }
}

// ---------------------------------------------------------------------------
// fused maxpool(3,2) + per-channel stats; LAST BLOCK computes scale/bias.
template <int CH, int PH>
__global__ void poolstats_kernel(const float* __restrict__ src,
                                 float* __restrict__ dst, int l,
                                 const float* __restrict__ gamma,
                                 const float* __restrict__ beta, double N) {
    __shared__ float r1[256], r2[256];
    __shared__ bool is_last;
    int bc = blockIdx.x;
    int c = bc & 63;
    const float* sb = src + (size_t)bc * CH * CH;
    float* db = dst + (size_t)bc * PH * PH;
    float s = 0.f, q = 0.f;
    for (int i = threadIdx.x; i < PH * PH; i += 256) {
        int py = i / PH, px = i - py * PH;
        const float* w = sb + (2 * py) * CH + 2 * px;
        float m = w[0];
#pragma unroll
        for (int di = 0; di < 3; di++)
#pragma unroll
            for (int dj = 0; dj < 3; dj++) m = fmaxf(m, w[di * CH + dj]);
        db[i] = m;
        s += m;
        q = fmaf(m, m, q);
    }
    r1[threadIdx.x] = s; r2[threadIdx.x] = q;
    __syncthreads();
    for (int o = 128; o > 0; o >>= 1) {
        if (threadIdx.x < o) {
            r1[threadIdx.x] += r1[threadIdx.x + o];
            r2[threadIdx.x] += r2[threadIdx.x + o];
        }
        __syncthreads();
    }
    if (threadIdx.x == 0) {
        atomicAdd(&g_dsum[c], (double)r1[0]);
        atomicAdd(&g_dsq[c], (double)r2[0]);
    }
    __threadfence();
    if (threadIdx.x == 0)
        is_last = (atomicAdd(&g_cnt1, 1) == (int)gridDim.x - 1);
    __syncthreads();
    if (!is_last) return;
    __threadfence();
    int cc = threadIdx.x;
    if (cc < 64) {
        double m = g_dsum[cc] / N;
        double var = g_dsq[cc] / N - m * m;
        double sc = (double)gamma[cc] / sqrt(var + 1e-5);
        g_scale[l][cc] = (float)sc;
        g_bias[l][cc] = (float)((double)beta[cc] - m * sc);
    }
    __syncthreads();
    if (cc < 64) { g_dsum[cc] = 0.0; g_dsq[cc] = 0.0; }
    if (cc == 0) g_cnt1 = 0;
}

// ---------------------------------------------------------------------------
// FC; LAST BLOCK runs sequential spectral normalization.
__global__ void fc_kernel(const float* __restrict__ Wreg,
                          const float* __restrict__ breg,
                          const float* __restrict__ u0,
                          const float* __restrict__ v0) {
    __shared__ float red[256];
    __shared__ bool is_last;
    int j = blockIdx.x % 6, b = blockIdx.x / 6;
    const float* pb = g_p3 + (size_t)b * 10816;
    const float* wb = Wreg + (size_t)j * 10816;
    float s = 0.f;
    for (int k = threadIdx.x; k < 10816; k += 256) {
        int c = k / 169;
        float v = fmaxf(fmaf(pb[k], g_scale[3][c], g_bias[3][c]), 0.f);
        s += v * wb[k];
    }
    red[threadIdx.x] = s;
    __syncthreads();
    for (int o = 128; o > 0; o >>= 1) {
        if (threadIdx.x < o) red[threadIdx.x] += red[threadIdx.x + o];
        __syncthreads();
    }
    if (threadIdx.x == 0) g_traw[b * 6 + j] = red[0] + breg[j];
    __threadfence();
    if (threadIdx.x == 0)
        is_last = (atomicAdd(&g_cnt2, 1) == (int)gridDim.x - 1);
    __syncthreads();
    if (!is_last) return;
    if (threadIdx.x != 0) return;
    __threadfence();
    g_cnt2 = 0;
    float u[2] = {u0[0], u0[1]};
    float v[3] = {v0[0], v0[1], v0[2]};
    for (int bb = 0; bb < 32; bb++) {
        float W[6];
#pragma unroll
        for (int i = 0; i < 6; i++) W[i] = g_traw[bb * 6 + i];
#pragma unroll
        for (int it = 0; it < 4; it++) {
            float nv[3];
#pragma unroll
            for (int jj = 0; jj < 3; jj++)
                nv[jj] = W[jj] * u[0] + W[3 + jj] * u[1];
            float n = sqrtf(nv[0] * nv[0] + nv[1] * nv[1] + nv[2] * nv[2]);
            n = fmaxf(n, 1e-12f);
#pragma unroll
            for (int jj = 0; jj < 3; jj++) v[jj] = nv[jj] / n;
            float nu0 = W[0] * v[0] + W[1] * v[1] + W[2] * v[2];
            float nu1 = W[3] * v[0] + W[4] * v[1] + W[5] * v[2];
            n = sqrtf(nu0 * nu0 + nu1 * nu1);
            n = fmaxf(n, 1e-12f);
            u[0] = nu0 / n; u[1] = nu1 / n;
        }
        float Wv0 = W[0] * v[0] + W[1] * v[1] + W[2] * v[2];
        float Wv1 = W[3] * v[0] + W[4] * v[1] + W[5] * v[2];
        float sigma = u[0] * Wv0 + u[1] * Wv1;
#pragma unroll
        for (int i = 0; i < 6; i++) g_theta[bb * 6 + i] = W[i] / sigma;
    }
}

// affine grid + reflection bilinear sample
__global__ void sample_kernel(const float* __restrict__ x,
                              float* __restrict__ out) {
    int idx = blockIdx.x * 256 + threadIdx.x;
    if (idx >= BATCH * 16384) return;
    int b = idx >> 14, p = idx & 16383;
    int h = p >> 7, w = p & 127;
    const float* th = &g_theta[b * 6];
    float xsc = (2.f * w + 1.f) / 128.f - 1.f;
    float ysc = (2.f * h + 1.f) / 128.f - 1.f;
    float gx = th[0] * xsc + th[1] * ysc + th[2];
    float gy = th[3] * xsc + th[4] * ysc + th[5];
    float ix = ((gx + 1.f) * 128.f - 1.f) * 0.5f;
    float iy = ((gy + 1.f) * 128.f - 1.f) * 0.5f;
    float r = fmodf(fabsf(ix + 0.5f), 256.f);
    ix = (r > 128.f ? 256.f - r : r) - 0.5f;
    ix = fminf(fmaxf(ix, 0.f), 127.f);
    r = fmodf(fabsf(iy + 0.5f), 256.f);
    iy = (r > 128.f ? 256.f - r : r) - 0.5f;
    iy = fminf(fmaxf(iy, 0.f), 127.f);
    float fx0 = floorf(ix), fy0 = floorf(iy);
    float wx = ix - fx0, wy = iy - fy0;
    int x0 = min(max((int)fx0, 0), 127), y0 = min(max((int)fy0, 0), 127);
    int x1 = min(x0 + 1, 127), y1 = min(y0 + 1, 127);
    float w00 = (1.f - wx) * (1.f - wy), w10 = wx * (1.f - wy);
    float w01 = (1.f - wx) * wy, w11 = wx * wy;
#pragma unroll
    for (int c = 0; c < 3; c++) {
        const float* xb = x + (size_t)(b * 3 + c) * 16384;
        float v = xb[y0 * 128 + x0] * w00 + xb[y0 * 128 + x1] * w10 +
                  xb[y1 * 128 + x0] * w01 + xb[y1 * 128 + x1] * w11;
        out[(size_t)(b * 3 + c) * 16384 + p] = v;
    }
}

// ---------------------------------------------------------------------------
extern "C" void kernel_launch(void* const* d_in, const int* in_sizes, int n_in,
                              void* d_out, int out_size) {
    const float* x     = (const float*)d_in[0];
    const float* w0    = (const float*)d_in[1];
    const float* w1    = (const float*)d_in[2];
    const float* w2    = (const float*)d_in[3];
    const float* w3    = (const float*)d_in[4];
    const float* gamma = (const float*)d_in[5];
    const float* beta  = (const float*)d_in[6];
    const float* Wreg  = (const float*)d_in[7];
    const float* breg  = (const float*)d_in[8];
    const float* u0    = (const float*)d_in[9];
    const float* v0    = (const float*)d_in[10];
    float* out = (float*)d_out;
    (void)n_in; (void)in_sizes; (void)out_size;

    float *pa1, *pp1, *pa2, *pp2, *pa3, *pp3;
    cudaGetSymbolAddress((void**)&pa1, g_a1);
    cudaGetSymbolAddress((void**)&pp1, g_p1);
    cudaGetSymbolAddress((void**)&pa2, g_a2);
    cudaGetSymbolAddress((void**)&pp2, g_p2);
    cudaGetSymbolAddress((void**)&pa3, g_a3);
    cudaGetSymbolAddress((void**)&pp3, g_p3);

    cudaFuncSetAttribute(conv1_mma_kernel,
                         cudaFuncAttributeMaxDynamicSharedMemorySize, C1_SMEM);

    // weight pre-split + stats(x) + fused analytic BN0
    wsplit_kernel<<<9, 256>>>(w1);
    statsx_kernel<<<512, 256>>>(x, w0, gamma, beta);

    // conv1 (HMMA fp16x2 implicit GEMM, fused conv0+bn0+relu) -> pool+stats+bn1
    conv1_mma_kernel<<<dim3(144, 32), 256, C1_SMEM>>>(x, w0, w1);
    poolstats_kernel<126, 62>
        <<<2048, 256>>>(pa1, pp1, 1, gamma + 64, beta + 64, 123008.0);

    // conv2 -> pool+stats+bn2
    conv3x3_kernel<62, 8><<<dim3(16, 32, 1), 256>>>(pp1, w2, pa2, 1);
    poolstats_kernel<60, 29>
        <<<2048, 256>>>(pa2, pp2, 2, gamma + 128, beta + 128, 26912.0);

    // conv3 (oc-split x2) -> pool+stats+bn3
    conv3x3_kernel<29, 4><<<dim3(4, 32, 2), 256>>>(pp2, w3, pa3, 2);
    poolstats_kernel<27, 13>
        <<<2048, 256>>>(pa3, pp3, 3, gamma + 192, beta + 192, 5408.0);

    // fc + fused spectral norm, then sampling
    fc_kernel<<<192, 256>>>(Wreg, breg, u0, v0);
    sample_kernel<<<(32 * 16384 + 255) / 256, 256>>>(x, out);
}

// round 15
// speedup vs baseline: 2.0406x; 1.2369x over previous
#include <cuda_runtime.h>
#include <cuda_fp16.h>
#include <math.h>
#include <stdint.h>

#define BATCH 32

// scratch (device globals: sanctioned workaround for no-alloc rule)
__device__ float g_a1[32 * 64 * 126 * 126];
__device__ float g_p1[32 * 64 * 62 * 62];
__device__ float g_a2[32 * 64 * 60 * 60];
__device__ float g_p2[32 * 64 * 29 * 29];
__device__ float g_a3[32 * 64 * 27 * 27];
__device__ float g_p3[32 * 64 * 13 * 13];
__device__ __align__(16) char g_Bs1[9][2][8192];  // pre-split swizzled w1
__device__ __align__(16) char g_Bs2[9][2][8192];  // pre-split swizzled w2
__device__ double g_dsum[64];
__device__ double g_dsq[64];
__device__ double g_xs[9];
__device__ float g_scale[4][64];
__device__ float g_bias[4][64];
__device__ float g_traw[32 * 6];
__device__ float g_theta[32 * 6];
__device__ int g_cnt0, g_cnt1, g_cnt2;

// ---------------------------------------------------------------------------
__device__ __forceinline__ uint32_t smem_to_u32(const void* p) {
    uint32_t a;
    asm("{ .reg .u64 t; cvta.to.shared.u64 t, %1; cvt.u32.u64 %0, t; }"
        : "=r"(a) : "l"(p));
    return a;
}
#define SMEM_SWIZZLE_128B(bo) ((bo) ^ (((bo) >> 3) & 0x70))

__device__ __forceinline__ void ldsm_x4(uint32_t* r, uint32_t addr) {
    asm volatile(
        "ldmatrix.sync.aligned.m8n8.x4.shared.b16 {%0,%1,%2,%3}, [%4];"
        : "=r"(r[0]), "=r"(r[1]), "=r"(r[2]), "=r"(r[3]) : "r"(addr));
}
__device__ __forceinline__ void ldsm_x4t(uint32_t* r, uint32_t addr) {
    asm volatile(
        "ldmatrix.sync.aligned.m8n8.x4.trans.shared.b16 {%0,%1,%2,%3}, [%4];"
        : "=r"(r[0]), "=r"(r[1]), "=r"(r[2]), "=r"(r[3]) : "r"(addr));
}
__device__ __forceinline__ void mma_f16(float* d, const uint32_t* a,
                                        const uint32_t* b) {
    asm volatile(
        "mma.sync.aligned.m16n8k16.row.col.f32.f16.f16.f32 "
        "{%0,%1,%2,%3}, {%4,%5,%6,%7}, {%8,%9}, {%0,%1,%2,%3};"
        : "+f"(d[0]), "+f"(d[1]), "+f"(d[2]), "+f"(d[3])
        : "r"(a[0]), "r"(a[1]), "r"(a[2]), "r"(a[3]), "r"(b[0]), "r"(b[1]));
}

// dynamic smem layout (bytes) for conv_mma
#define C1_XS 0        // float[540]            (2160)
#define C1_H1 2176     // fp16 [180][64] SW128  (23040)
#define C1_H2 25216
#define C1_B1 48256    // fp16 [64][64] SW128   (8192)
#define C1_B2 56448
#define C1_SMEM 64640

// ---------------------------------------------------------------------------
// pre-split w1/w2 into 2 fp16 planes per tap, SW128-swizzled [cin][cout]
__global__ void wsplit_kernel(const float* __restrict__ w1,
                              const float* __restrict__ w2) {
    int s = blockIdx.x;
    const float* w = (blockIdx.y == 0) ? w1 : w2;
    char (*Bs)[2][8192] = (blockIdx.y == 0) ? g_Bs1 : g_Bs2;
    for (int idx = threadIdx.x; idx < 4096; idx += 256) {
        int oc = idx >> 6, cin = idx & 63;
        float wv = w[(oc * 64 + cin) * 9 + s];
        __half w1h = __float2half(wv);
        __half w2h = __float2half(wv - __half2float(w1h));
        uint32_t off = SMEM_SWIZZLE_128B((uint32_t)(cin * 128 + oc * 2));
        *(__half*)(&Bs[s][0][off]) = w1h;
        *(__half*)(&Bs[s][1][off]) = w2h;
    }
}

// ---------------------------------------------------------------------------
// statsx: second moments of x via warp shuffles; LAST BLOCK computes BN0.
__global__ void statsx_kernel(const float* __restrict__ x,
                              const float* __restrict__ w0,
                              const float* __restrict__ gamma,
                              const float* __restrict__ beta) {
    __shared__ float wred[8][9];
    __shared__ bool is_last;
    float a[9];
#pragma unroll
    for (int i = 0; i < 9; i++) a[i] = 0.f;
    for (int idx = blockIdx.x * 256 + threadIdx.x; idx < BATCH * 16384;
         idx += gridDim.x * 256) {
        int b = idx >> 14, p = idx & 16383;
        float x0 = x[(b * 3 + 0) * 16384 + p];
        float x1 = x[(b * 3 + 1) * 16384 + p];
        float x2 = x[(b * 3 + 2) * 16384 + p];
        a[0] = fmaf(x0, x0, a[0]); a[1] = fmaf(x0, x1, a[1]);
        a[2] = fmaf(x0, x2, a[2]); a[3] = fmaf(x1, x1, a[3]);
        a[4] = fmaf(x1, x2, a[4]); a[5] = fmaf(x2, x2, a[5]);
        a[6] += x0; a[7] += x1; a[8] += x2;
    }
    int lane = threadIdx.x & 31, wid = threadIdx.x >> 5;
#pragma unroll
    for (int q = 0; q < 9; q++) {
#pragma unroll
        for (int o = 16; o > 0; o >>= 1)
            a[q] += __shfl_xor_sync(0xffffffffu, a[q], o);
        if (lane == 0) wred[wid][q] = a[q];
    }
    __syncthreads();
    if (threadIdx.x < 9) {
        float s = 0.f;
#pragma unroll
        for (int w = 0; w < 8; w++) s += wred[w][threadIdx.x];
        atomicAdd(&g_xs[threadIdx.x], (double)s);
    }
    __threadfence();
    if (threadIdx.x == 0)
        is_last = (atomicAdd(&g_cnt0, 1) == (int)gridDim.x - 1);
    __syncthreads();
    if (!is_last) return;
    __threadfence();
    int o = threadIdx.x;
    if (o < 64) {
        const double N = 524288.0;
        double C00 = g_xs[0] / N, C01 = g_xs[1] / N, C02 = g_xs[2] / N;
        double C11 = g_xs[3] / N, C12 = g_xs[4] / N, C22 = g_xs[5] / N;
        double m0 = g_xs[6] / N, m1 = g_xs[7] / N, m2 = g_xs[8] / N;
        double w0v = w0[o * 3 + 0], w1v = w0[o * 3 + 1], w2v = w0[o * 3 + 2];
        double m = w0v * m0 + w1v * m1 + w2v * m2;
        double e2 = w0v * w0v * C00 + w1v * w1v * C11 + w2v * w2v * C22 +
                    2.0 * (w0v * w1v * C01 + w0v * w2v * C02 + w1v * w2v * C12);
        double var = e2 - m * m;
        double sc = (double)gamma[o] / sqrt(var + 1e-5);
        g_scale[0][o] = (float)sc;
        g_bias[0][o] = (float)((double)beta[o] - m * sc);
    }
    __syncthreads();
    if (threadIdx.x < 9) g_xs[threadIdx.x] = 0.0;
    if (threadIdx.x == 0) g_cnt0 = 0;
}

// ---------------------------------------------------------------------------
// conv via mma.sync, fp16 2-plane split (3 products), 9 taps, implicit GEMM.
// Block: 256 thr (8 warps), M=128 pixel rows (7x18 span), N=64 couts, K=64/tap.
// C1=true: input = relu(bn0(conv0(x))) computed in-kernel from x.
// C1=false: input = relu(bn_lidx(src)) loaded from a 64-channel feature map.
template <int IH, bool C1>
__global__ __launch_bounds__(256, 2) void conv_mma_kernel(
    const float* __restrict__ src, const float* __restrict__ w0,
    const char* __restrict__ Bplanes, float* __restrict__ dst, int lidx) {
    constexpr int OH = IH - 2;
    constexpr int TX = (OH + 15) / 16;
    extern __shared__ char smem[];
    float* xs = (float*)(smem + C1_XS);
    const uint32_t h1_b = smem_to_u32(smem + C1_H1);
    const uint32_t h2_b = smem_to_u32(smem + C1_H2);
    const uint32_t b1_b = smem_to_u32(smem + C1_B1);
    const uint32_t b2_b = smem_to_u32(smem + C1_B2);
    const int tid = threadIdx.x;
    const int lane = tid & 31, mw = tid >> 5;
    const int b = blockIdx.y;
    const int tx = blockIdx.x % TX, ty = blockIdx.x / TX;
    const int y0 = ty * 7, x0 = tx * 16;

    if (C1) {
        for (int idx = tid; idx < 540; idx += 256) {
            int c = idx / 180, p = idx - c * 180;
            int ry = p / 20, rx = p - ry * 20;
            int gx = x0 + rx;
            float v = 0.f;
            if (gx < IH) v = src[((b * 3 + c) * IH + (y0 + ry)) * IH + gx];
            xs[c * 180 + p] = v;
        }
        __syncthreads();
    }

    // stage input (bn+relu), fp16 2-plane split into [px][cin] SW128 layout
    {
        int j = lane;
        int c0 = 2 * j, c1 = 2 * j + 1;
        float s0 = g_scale[lidx][c0], bb0 = g_bias[lidx][c0];
        float s1 = g_scale[lidx][c1], bb1 = g_bias[lidx][c1];
        float a00, a01, a02, a10, a11, a12;
        const float *sb0, *sb1;
        if (C1) {
            a00 = w0[c0 * 3]; a01 = w0[c0 * 3 + 1]; a02 = w0[c0 * 3 + 2];
            a10 = w0[c1 * 3]; a11 = w0[c1 * 3 + 1]; a12 = w0[c1 * 3 + 2];
        } else {
            sb0 = src + ((size_t)(b * 64 + c0)) * IH * IH;
            sb1 = src + ((size_t)(b * 64 + c1)) * IH * IH;
        }
        for (int p = mw; p < 180; p += 8) {
            float v0, v1;
            if (C1) {
                float xv0 = xs[p], xv1 = xs[180 + p], xv2 = xs[360 + p];
                v0 = xv0 * a00 + xv1 * a01 + xv2 * a02;
                v1 = xv0 * a10 + xv1 * a11 + xv2 * a12;
            } else {
                int ry = p / 20, rx = p - ry * 20;
                int gy = y0 + ry, gx = x0 + rx;
                v0 = 0.f; v1 = 0.f;
                if (gy < IH && gx < IH) {
                    v0 = sb0[gy * IH + gx];
                    v1 = sb1[gy * IH + gx];
                }
            }
            v0 = fmaxf(fmaf(v0, s0, bb0), 0.f);
            v1 = fmaxf(fmaf(v1, s1, bb1), 0.f);
            __half p0 = __float2half(v0);
            __half q0 = __float2half(v0 - __half2float(p0));
            __half p1 = __float2half(v1);
            __half q1 = __float2half(v1 - __half2float(p1));
            uint32_t off = SMEM_SWIZZLE_128B((uint32_t)(p * 128 + j * 4));
            *(uint32_t*)(smem + C1_H1 + off) =
                (uint32_t)__half_as_ushort(p0) |
                ((uint32_t)__half_as_ushort(p1) << 16);
            *(uint32_t*)(smem + C1_H2 + off) =
                (uint32_t)__half_as_ushort(q0) |
                ((uint32_t)__half_as_ushort(q1) << 16);
        }
    }

    float acc[8][4];
#pragma unroll
    for (int j = 0; j < 8; j++)
#pragma unroll
        for (int q = 0; q < 4; q++) acc[j][q] = 0.f;

    for (int s = 0; s < 9; s++) {
        __syncthreads();  // h ready (s=0) / previous tap's ldmatrix done (s>0)
        for (int idx = tid; idx < 1024; idx += 256) {
            int pl = idx >> 9, q = idx & 511;
            ((uint4*)(smem + C1_B1 + pl * 8192))[q] =
                ((const uint4*)(Bplanes + (s * 2 + pl) * 8192))[q];
        }
        __syncthreads();

        int ky = s / 3, kx = s - ky * 3;
        int m = mw * 16 + (lane & 15);
        int p = 0;
        if (m < 126) {
            int my = m / 18, mx = m - my * 18;
            p = (my + ky) * 20 + (mx + kx);
        }
        uint32_t arow = (uint32_t)(p * 128) + ((uint32_t)(lane >> 4) << 4);
#pragma unroll
        for (int kk = 0; kk < 4; kk++) {
            uint32_t a1[4], a2[4];
            uint32_t ao = SMEM_SWIZZLE_128B(arow + kk * 32);
            ldsm_x4(a1, h1_b + ao);
            ldsm_x4(a2, h2_b + ao);
            uint32_t brow = (uint32_t)((kk * 16 + (lane & 15)) * 128) +
                            ((uint32_t)(lane >> 4) << 4);
#pragma unroll
            for (int jp = 0; jp < 4; jp++) {
                uint32_t bb1[4], bb2[4];
                uint32_t bo = SMEM_SWIZZLE_128B(brow + jp * 32);
                ldsm_x4t(bb1, b1_b + bo);
                ldsm_x4t(bb2, b2_b + bo);
                mma_f16(acc[2 * jp], a1, bb1);
                mma_f16(acc[2 * jp], a1, bb2);
                mma_f16(acc[2 * jp], a2, bb1);
                mma_f16(acc[2 * jp + 1], a1, bb1 + 2);
                mma_f16(acc[2 * jp + 1], a1, bb2 + 2);
                mma_f16(acc[2 * jp + 1], a2, bb1 + 2);
            }
        }
    }

    // epilogue: transpose through smem for coalesced global stores
    __syncthreads();
    float* buf = (float*)smem;  // [128][65]
    int r0 = mw * 16 + (lane >> 2);
    int c0 = (lane & 3) * 2;
#pragma unroll
    for (int j = 0; j < 8; j++) {
        int oc = j * 8 + c0;
        buf[r0 * 65 + oc] = acc[j][0];
        buf[r0 * 65 + oc + 1] = acc[j][1];
        buf[(r0 + 8) * 65 + oc] = acc[j][2];
        buf[(r0 + 8) * 65 + oc + 1] = acc[j][3];
    }
    __syncthreads();
    for (int idx = tid; idx < 64 * 126; idx += 256) {
        int oc = idx / 126, m = idx - oc * 126;
        int my = m / 18, mx = m - my * 18;
        if (mx >= 16) continue;
        int oy = y0 + my, ox = x0 + mx;
        if (ox >= OH || oy >= OH) continue;
        dst[((size_t)(b * 64 + oc) * OH + oy) * OH + ox] = buf[m * 65 + oc];
    }
}

// ---------------------------------------------------------------------------
// conv inner: OCB out-channels x (2 rows x 4 cols) per thread, 9 taps
template <int OCB>
__device__ __forceinline__ void conv_tile_accum(const float* __restrict__ in_s,
                                                const float* __restrict__ ws,
                                                float acc[OCB][8], int cg,
                                                int ry, int cx) {
    float vin[4][6];
#pragma unroll
    for (int r = 0; r < 4; r++) {
        const float* ip = &in_s[(ry + r) * 20 + cx];
#pragma unroll
        for (int c = 0; c < 6; c++) vin[r][c] = ip[c];
    }
#pragma unroll
    for (int ch = 0; ch < OCB; ch++) {
        const float* wp = &ws[(cg * OCB + ch) * 12];
        float w[9];
#pragma unroll
        for (int t = 0; t < 9; t++) w[t] = wp[t];
#pragma unroll
        for (int r = 0; r < 2; r++) {
#pragma unroll
            for (int c = 0; c < 4; c++) {
                float s = acc[ch][r * 4 + c];
                s = fmaf(vin[r][c],     w[0], s);
                s = fmaf(vin[r][c + 1], w[1], s);
                s = fmaf(vin[r][c + 2], w[2], s);
                s = fmaf(vin[r + 1][c],     w[3], s);
                s = fmaf(vin[r + 1][c + 1], w[4], s);
                s = fmaf(vin[r + 1][c + 2], w[5], s);
                s = fmaf(vin[r + 2][c],     w[6], s);
                s = fmaf(vin[r + 2][c + 1], w[7], s);
                s = fmaf(vin[r + 2][c + 2], w[8], s);
                acc[ch][r * 4 + c] = s;
            }
        }
    }
}

// generic 3x3 conv (direct); quad-buffered staging
template <int IH, int OCB>
__global__ __launch_bounds__(256, 2) void conv3x3_kernel(
    const float* __restrict__ src, const float* __restrict__ wconv,
    float* __restrict__ dst, int lidx) {
    constexpr int OH = IH - 2;
    constexpr int TX = (OH + 15) / 16;
    constexpr int NOC = 8 * OCB;
    __shared__ float in_s[4][360];
    __shared__ float ws[4][NOC * 12];
    const int b = blockIdx.y;
    const int oc0 = blockIdx.z * NOC;
    const int tx = blockIdx.x % TX, ty = blockIdx.x / TX;
    const int oy0 = ty * 16, ox0 = tx * 16;
    const int tid = threadIdx.x;
    const int cg = tid >> 5;
    const int sp = tid & 31;
    const int ry = (sp >> 2) * 2, cx = (sp & 3) * 4;

    float acc[OCB][8];
#pragma unroll
    for (int i = 0; i < OCB; i++)
#pragma unroll
        for (int j = 0; j < 8; j++) acc[i][j] = 0.f;

    auto stage = [&](int cin, int bf) {
        float scl = g_scale[lidx][cin], bia = g_bias[lidx][cin];
        const float* sb = src + ((size_t)(b * 64 + cin)) * IH * IH;
        for (int idx = tid; idx < 324; idx += 256) {
            int iy = idx / 18, ix = idx - iy * 18;
            int gy = oy0 + iy, gx = ox0 + ix;
            float v = 0.f;
            if (gy < IH && gx < IH) v = sb[gy * IH + gx];
            in_s[bf][iy * 20 + ix] = fmaxf(fmaf(v, scl, bia), 0.f);
        }
        for (int idx = tid; idx < NOC * 9; idx += 256) {
            int o = idx / 9, t = idx - o * 9;
            ws[bf][o * 12 + t] = wconv[((oc0 + o) * 64 + cin) * 9 + t];
        }
    };

    stage(0, 0);
    stage(1, 1);
    __syncthreads();
    for (int cin = 0; cin < 64; cin += 2) {
        if (cin + 2 < 64) {
            stage(cin + 2, (cin + 2) & 3);
            stage(cin + 3, (cin + 3) & 3);
        }
        conv_tile_accum<OCB>(in_s[cin & 3], ws[cin & 3], acc, cg, ry, cx);
        conv_tile_accum<OCB>(in_s[(cin + 1) & 3], ws[(cin + 1) & 3], acc, cg,
                             ry, cx);
        __syncthreads();
    }

#pragma unroll
    for (int ch = 0; ch < OCB; ch++) {
        const int och = oc0 + cg * OCB + ch;
        float* db = dst + ((size_t)(b * 64 + och)) * OH * OH;
#pragma unroll
        for (int r = 0; r < 2; r++) {
            int oy = oy0 + ry + r;
            if (oy >= OH) continue;
#pragma unroll
            for (int c = 0; c < 4; c++) {
                int ox = ox0 + cx + c;
                if (ox < OH) db[oy * OH + ox] = acc[ch][r * 4 + c];
            }
        }
    }
}

// ---------------------------------------------------------------------------
// fused maxpool(3,2) + per-channel stats; LAST BLOCK computes scale/bias.
template <int CH, int PH>
__global__ void poolstats_kernel(const float* __restrict__ src,
                                 float* __restrict__ dst, int l,
                                 const float* __restrict__ gamma,
                                 const float* __restrict__ beta, double N) {
    __shared__ float r1[256], r2[256];
    __shared__ bool is_last;
    int bc = blockIdx.x;
    int c = bc & 63;
    const float* sb = src + (size_t)bc * CH * CH;
    float* db = dst + (size_t)bc * PH * PH;
    float s = 0.f, q = 0.f;
    for (int i = threadIdx.x; i < PH * PH; i += 256) {
        int py = i / PH, px = i - py * PH;
        const float* w = sb + (2 * py) * CH + 2 * px;
        float m = w[0];
#pragma unroll
        for (int di = 0; di < 3; di++)
#pragma unroll
            for (int dj = 0; dj < 3; dj++) m = fmaxf(m, w[di * CH + dj]);
        db[i] = m;
        s += m;
        q = fmaf(m, m, q);
    }
    r1[threadIdx.x] = s; r2[threadIdx.x] = q;
    __syncthreads();
    for (int o = 128; o > 0; o >>= 1) {
        if (threadIdx.x < o) {
            r1[threadIdx.x] += r1[threadIdx.x + o];
            r2[threadIdx.x] += r2[threadIdx.x + o];
        }
        __syncthreads();
    }
    if (threadIdx.x == 0) {
        atomicAdd(&g_dsum[c], (double)r1[0]);
        atomicAdd(&g_dsq[c], (double)r2[0]);
    }
    __threadfence();
    if (threadIdx.x == 0)
        is_last = (atomicAdd(&g_cnt1, 1) == (int)gridDim.x - 1);
    __syncthreads();
    if (!is_last) return;
    __threadfence();
    int cc = threadIdx.x;
    if (cc < 64) {
        double m = g_dsum[cc] / N;
        double var = g_dsq[cc] / N - m * m;
        double sc = (double)gamma[cc] / sqrt(var + 1e-5);
        g_scale[l][cc] = (float)sc;
        g_bias[l][cc] = (float)((double)beta[cc] - m * sc);
    }
    __syncthreads();
    if (cc < 64) { g_dsum[cc] = 0.0; g_dsq[cc] = 0.0; }
    if (cc == 0) g_cnt1 = 0;
}

// ---------------------------------------------------------------------------
// FC; LAST BLOCK runs sequential spectral normalization.
__global__ void fc_kernel(const float* __restrict__ Wreg,
                          const float* __restrict__ breg,
                          const float* __restrict__ u0,
                          const float* __restrict__ v0) {
    __shared__ float red[256];
    __shared__ bool is_last;
    int j = blockIdx.x % 6, b = blockIdx.x / 6;
    const float* pb = g_p3 + (size_t)b * 10816;
    const float* wb = Wreg + (size_t)j * 10816;
    float s = 0.f;
    for (int k = threadIdx.x; k < 10816; k += 256) {
        int c = k / 169;
        float v = fmaxf(fmaf(pb[k], g_scale[3][c], g_bias[3][c]), 0.f);
        s += v * wb[k];
    }
    red[threadIdx.x] = s;
    __syncthreads();
    for (int o = 128; o > 0; o >>= 1) {
        if (threadIdx.x < o) red[threadIdx.x] += red[threadIdx.x + o];
        __syncthreads();
    }
    if (threadIdx.x == 0) g_traw[b * 6 + j] = red[0] + breg[j];
    __threadfence();
    if (threadIdx.x == 0)
        is_last = (atomicAdd(&g_cnt2, 1) == (int)gridDim.x - 1);
    __syncthreads();
    if (!is_last) return;
    if (threadIdx.x != 0) return;
    __threadfence();
    g_cnt2 = 0;
    float u[2] = {u0[0], u0[1]};
    float v[3] = {v0[0], v0[1], v0[2]};
    for (int bb = 0; bb < 32; bb++) {
        float W[6];
#pragma unroll
        for (int i = 0; i < 6; i++) W[i] = g_traw[bb * 6 + i];
#pragma unroll
        for (int it = 0; it < 4; it++) {
            float nv[3];
#pragma unroll
            for (int jj = 0; jj < 3; jj++)
                nv[jj] = W[jj] * u[0] + W[3 + jj] * u[1];
            float n = sqrtf(nv[0] * nv[0] + nv[1] * nv[1] + nv[2] * nv[2]);
            n = fmaxf(n, 1e-12f);
#pragma unroll
            for (int jj = 0; jj < 3; jj++) v[jj] = nv[jj] / n;
            float nu0 = W[0] * v[0] + W[1] * v[1] + W[2] * v[2];
            float nu1 = W[3] * v[0] + W[4] * v[1] + W[5] * v[2];
            n = sqrtf(nu0 * nu0 + nu1 * nu1);
            n = fmaxf(n, 1e-12f);
            u[0] = nu0 / n; u[1] = nu1 / n;
        }
        float Wv0 = W[0] * v[0] + W[1] * v[1] + W[2] * v[2];
        float Wv1 = W[3] * v[0] + W[4] * v[1] + W[5] * v[2];
        float sigma = u[0] * Wv0 + u[1] * Wv1;
#pragma unroll
        for (int i = 0; i < 6; i++) g_theta[bb * 6 + i] = W[i] / sigma;
    }
}

// affine grid + reflection bilinear sample
__global__ void sample_kernel(const float* __restrict__ x,
                              float* __restrict__ out) {
    int idx = blockIdx.x * 256 + threadIdx.x;
    if (idx >= BATCH * 16384) return;
    int b = idx >> 14, p = idx & 16383;
    int h = p >> 7, w = p & 127;
    const float* th = &g_theta[b * 6];
    float xsc = (2.f * w + 1.f) / 128.f - 1.f;
    float ysc = (2.f * h + 1.f) / 128.f - 1.f;
    float gx = th[0] * xsc + th[1] * ysc + th[2];
    float gy = th[3] * xsc + th[4] * ysc + th[5];
    float ix = ((gx + 1.f) * 128.f - 1.f) * 0.5f;
    float iy = ((gy + 1.f) * 128.f - 1.f) * 0.5f;
    float r = fmodf(fabsf(ix + 0.5f), 256.f);
    ix = (r > 128.f ? 256.f - r : r) - 0.5f;
    ix = fminf(fmaxf(ix, 0.f), 127.f);
    r = fmodf(fabsf(iy + 0.5f), 256.f);
    iy = (r > 128.f ? 256.f - r : r) - 0.5f;
    iy = fminf(fmaxf(iy, 0.f), 127.f);
    float fx0 = floorf(ix), fy0 = floorf(iy);
    float wx = ix - fx0, wy = iy - fy0;
    int x0 = min(max((int)fx0, 0), 127), y0 = min(max((int)fy0, 0), 127);
    int x1 = min(x0 + 1, 127), y1 = min(y0 + 1, 127);
    float w00 = (1.f - wx) * (1.f - wy), w10 = wx * (1.f - wy);
    float w01 = (1.f - wx) * wy, w11 = wx * wy;
#pragma unroll
    for (int c = 0; c < 3; c++) {
        const float* xb = x + (size_t)(b * 3 + c) * 16384;
        float v = xb[y0 * 128 + x0] * w00 + xb[y0 * 128 + x1] * w10 +
                  xb[y1 * 128 + x0] * w01 + xb[y1 * 128 + x1] * w11;
        out[(size_t)(b * 3 + c) * 16384 + p] = v;
    }
}

// ---------------------------------------------------------------------------
extern "C" void kernel_launch(void* const* d_in, const int* in_sizes, int n_in,
                              void* d_out, int out_size) {
    const float* x     = (const float*)d_in[0];
    const float* w0    = (const float*)d_in[1];
    const float* w1    = (const float*)d_in[2];
    const float* w2    = (const float*)d_in[3];
    const float* w3    = (const float*)d_in[4];
    const float* gamma = (const float*)d_in[5];
    const float* beta  = (const float*)d_in[6];
    const float* Wreg  = (const float*)d_in[7];
    const float* breg  = (const float*)d_in[8];
    const float* u0    = (const float*)d_in[9];
    const float* v0    = (const float*)d_in[10];
    float* out = (float*)d_out;
    (void)n_in; (void)in_sizes; (void)out_size;

    float *pa1, *pp1, *pa2, *pp2, *pa3, *pp3;
    char *pB1, *pB2;
    cudaGetSymbolAddress((void**)&pa1, g_a1);
    cudaGetSymbolAddress((void**)&pp1, g_p1);
    cudaGetSymbolAddress((void**)&pa2, g_a2);
    cudaGetSymbolAddress((void**)&pp2, g_p2);
    cudaGetSymbolAddress((void**)&pa3, g_a3);
    cudaGetSymbolAddress((void**)&pp3, g_p3);
    cudaGetSymbolAddress((void**)&pB1, g_Bs1);
    cudaGetSymbolAddress((void**)&pB2, g_Bs2);

    cudaFuncSetAttribute(conv_mma_kernel<128, true>,
                         cudaFuncAttributeMaxDynamicSharedMemorySize, C1_SMEM);
    cudaFuncSetAttribute(conv_mma_kernel<62, false>,
                         cudaFuncAttributeMaxDynamicSharedMemorySize, C1_SMEM);

    // weight pre-split + stats(x) + fused analytic BN0
    wsplit_kernel<<<dim3(9, 2), 256>>>(w1, w2);
    statsx_kernel<<<512, 256>>>(x, w0, gamma, beta);

    // conv1 (HMMA fp16x2, fused conv0+bn0+relu) -> pool+stats+bn1
    conv_mma_kernel<128, true>
        <<<dim3(144, 32), 256, C1_SMEM>>>(x, w0, pB1, pa1, 0);
    poolstats_kernel<126, 62>
        <<<2048, 256>>>(pa1, pp1, 1, gamma + 64, beta + 64, 123008.0);

    // conv2 (HMMA fp16x2, fused bn1+relu on load) -> pool+stats+bn2
    conv_mma_kernel<62, false>
        <<<dim3(36, 32), 256, C1_SMEM>>>(pp1, w0, pB2, pa2, 1);
    poolstats_kernel<60, 29>
        <<<2048, 256>>>(pa2, pp2, 2, gamma + 128, beta + 128, 26912.0);

    // conv3 (direct, oc-split x2) -> pool+stats+bn3
    conv3x3_kernel<29, 4><<<dim3(4, 32, 2), 256>>>(pp2, w3, pa3, 2);
    poolstats_kernel<27, 13>
        <<<2048, 256>>>(pa3, pp3, 3, gamma + 192, beta + 192, 5408.0);

    // fc + fused spectral norm, then sampling
    fc_kernel<<<192, 256>>>(Wreg, breg, u0, v0);
    sample_kernel<<<(32 * 16384 + 255) / 256, 256>>>(x, out);
}

// round 16
// speedup vs baseline: 2.2023x; 1.0792x over previous
#include <cuda_runtime.h>
#include <cuda_fp16.h>
#include <math.h>
#include <stdint.h>

#define BATCH 32

// scratch (device globals: sanctioned workaround for no-alloc rule)
__device__ float g_a1[32 * 64 * 126 * 126];
__device__ float g_p1[32 * 64 * 62 * 62];
__device__ float g_a2[32 * 64 * 60 * 60];
__device__ float g_p2[32 * 64 * 29 * 29];
__device__ float g_a3[32 * 64 * 27 * 27];
__device__ float g_p3[32 * 64 * 13 * 13];
__device__ __align__(16) char g_Bs1[9][2][8192];  // pre-split swizzled w1
__device__ __align__(16) char g_Bs2[9][2][8192];  // pre-split swizzled w2
__device__ __align__(16) char g_Bs3[9][2][8192];  // pre-split swizzled w3
__device__ double g_dsum[64];
__device__ double g_dsq[64];
__device__ double g_xs[9];
__device__ float g_scale[4][64];
__device__ float g_bias[4][64];
__device__ float g_traw[32 * 6];
__device__ float g_theta[32 * 6];
__device__ int g_cnt0, g_cnt1, g_cnt2;

// ---------------------------------------------------------------------------
__device__ __forceinline__ uint32_t smem_to_u32(const void* p) {
    uint32_t a;
    asm("{ .reg .u64 t; cvta.to.shared.u64 t, %1; cvt.u32.u64 %0, t; }"
        : "=r"(a) : "l"(p));
    return a;
}
#define SMEM_SWIZZLE_128B(bo) ((bo) ^ (((bo) >> 3) & 0x70))

__device__ __forceinline__ void ldsm_x4(uint32_t* r, uint32_t addr) {
    asm volatile(
        "ldmatrix.sync.aligned.m8n8.x4.shared.b16 {%0,%1,%2,%3}, [%4];"
        : "=r"(r[0]), "=r"(r[1]), "=r"(r[2]), "=r"(r[3]) : "r"(addr));
}
__device__ __forceinline__ void ldsm_x4t(uint32_t* r, uint32_t addr) {
    asm volatile(
        "ldmatrix.sync.aligned.m8n8.x4.trans.shared.b16 {%0,%1,%2,%3}, [%4];"
        : "=r"(r[0]), "=r"(r[1]), "=r"(r[2]), "=r"(r[3]) : "r"(addr));
}
__device__ __forceinline__ void mma_f16(float* d, const uint32_t* a,
                                        const uint32_t* b) {
    asm volatile(
        "mma.sync.aligned.m16n8k16.row.col.f32.f16.f16.f32 "
        "{%0,%1,%2,%3}, {%4,%5,%6,%7}, {%8,%9}, {%0,%1,%2,%3};"
        : "+f"(d[0]), "+f"(d[1]), "+f"(d[2]), "+f"(d[3])
        : "r"(a[0]), "r"(a[1]), "r"(a[2]), "r"(a[3]), "r"(b[0]), "r"(b[1]));
}

// dynamic smem layout (bytes) for conv_mma
#define C1_XS 0        // float[540]            (2160)
#define C1_H1 2176     // fp16 [180][64] SW128  (23040)
#define C1_H2 25216
#define C1_B 48256     // [2 bufs][2 planes][8192] = 32768
#define C1_SMEM 81024

// ---------------------------------------------------------------------------
// pre-split w1/w2/w3 into 2 fp16 planes per tap, SW128-swizzled [cin][cout]
__global__ void wsplit_kernel(const float* __restrict__ w1,
                              const float* __restrict__ w2,
                              const float* __restrict__ w3) {
    int s = blockIdx.x;
    const float* w = (blockIdx.y == 0) ? w1 : (blockIdx.y == 1) ? w2 : w3;
    char (*Bs)[2][8192] =
        (blockIdx.y == 0) ? g_Bs1 : (blockIdx.y == 1) ? g_Bs2 : g_Bs3;
    for (int idx = threadIdx.x; idx < 4096; idx += 256) {
        int oc = idx >> 6, cin = idx & 63;
        float wv = w[(oc * 64 + cin) * 9 + s];
        __half w1h = __float2half(wv);
        __half w2h = __float2half(wv - __half2float(w1h));
        uint32_t off = SMEM_SWIZZLE_128B((uint32_t)(cin * 128 + oc * 2));
        *(__half*)(&Bs[s][0][off]) = w1h;
        *(__half*)(&Bs[s][1][off]) = w2h;
    }
}

// ---------------------------------------------------------------------------
// statsx: second moments of x via warp shuffles; LAST BLOCK computes BN0.
__global__ void statsx_kernel(const float* __restrict__ x,
                              const float* __restrict__ w0,
                              const float* __restrict__ gamma,
                              const float* __restrict__ beta) {
    __shared__ float wred[8][9];
    __shared__ bool is_last;
    float a[9];
#pragma unroll
    for (int i = 0; i < 9; i++) a[i] = 0.f;
    for (int idx = blockIdx.x * 256 + threadIdx.x; idx < BATCH * 16384;
         idx += gridDim.x * 256) {
        int b = idx >> 14, p = idx & 16383;
        float x0 = x[(b * 3 + 0) * 16384 + p];
        float x1 = x[(b * 3 + 1) * 16384 + p];
        float x2 = x[(b * 3 + 2) * 16384 + p];
        a[0] = fmaf(x0, x0, a[0]); a[1] = fmaf(x0, x1, a[1]);
        a[2] = fmaf(x0, x2, a[2]); a[3] = fmaf(x1, x1, a[3]);
        a[4] = fmaf(x1, x2, a[4]); a[5] = fmaf(x2, x2, a[5]);
        a[6] += x0; a[7] += x1; a[8] += x2;
    }
    int lane = threadIdx.x & 31, wid = threadIdx.x >> 5;
#pragma unroll
    for (int q = 0; q < 9; q++) {
#pragma unroll
        for (int o = 16; o > 0; o >>= 1)
            a[q] += __shfl_xor_sync(0xffffffffu, a[q], o);
        if (lane == 0) wred[wid][q] = a[q];
    }
    __syncthreads();
    if (threadIdx.x < 9) {
        float s = 0.f;
#pragma unroll
        for (int w = 0; w < 8; w++) s += wred[w][threadIdx.x];
        atomicAdd(&g_xs[threadIdx.x], (double)s);
    }
    __threadfence();
    if (threadIdx.x == 0)
        is_last = (atomicAdd(&g_cnt0, 1) == (int)gridDim.x - 1);
    __syncthreads();
    if (!is_last) return;
    __threadfence();
    int o = threadIdx.x;
    if (o < 64) {
        const double N = 524288.0;
        double C00 = g_xs[0] / N, C01 = g_xs[1] / N, C02 = g_xs[2] / N;
        double C11 = g_xs[3] / N, C12 = g_xs[4] / N, C22 = g_xs[5] / N;
        double m0 = g_xs[6] / N, m1 = g_xs[7] / N, m2 = g_xs[8] / N;
        double w0v = w0[o * 3 + 0], w1v = w0[o * 3 + 1], w2v = w0[o * 3 + 2];
        double m = w0v * m0 + w1v * m1 + w2v * m2;
        double e2 = w0v * w0v * C00 + w1v * w1v * C11 + w2v * w2v * C22 +
                    2.0 * (w0v * w1v * C01 + w0v * w2v * C02 + w1v * w2v * C12);
        double var = e2 - m * m;
        double sc = (double)gamma[o] / sqrt(var + 1e-5);
        g_scale[0][o] = (float)sc;
        g_bias[0][o] = (float)((double)beta[o] - m * sc);
    }
    __syncthreads();
    if (threadIdx.x < 9) g_xs[threadIdx.x] = 0.0;
    if (threadIdx.x == 0) g_cnt0 = 0;
}

// ---------------------------------------------------------------------------
// conv via mma.sync, fp16 2-plane split (3 products), 9 taps, implicit GEMM.
// Block: 256 thr (8 warps), M=128 pixel rows (7x18 span), N=64 couts, K=64/tap.
// B weight planes double-buffered: copy tap s+1 while mma on tap s.
template <int IH, bool C1>
__global__ __launch_bounds__(256, 2) void conv_mma_kernel(
    const float* __restrict__ src, const float* __restrict__ w0,
    const char* __restrict__ Bplanes, float* __restrict__ dst, int lidx) {
    constexpr int OH = IH - 2;
    constexpr int TX = (OH + 15) / 16;
    extern __shared__ char smem[];
    float* xs = (float*)(smem + C1_XS);
    const uint32_t h1_b = smem_to_u32(smem + C1_H1);
    const uint32_t h2_b = smem_to_u32(smem + C1_H2);
    const uint32_t bB = smem_to_u32(smem + C1_B);
    const int tid = threadIdx.x;
    const int lane = tid & 31, mw = tid >> 5;
    const int b = blockIdx.y;
    const int tx = blockIdx.x % TX, ty = blockIdx.x / TX;
    const int y0 = ty * 7, x0 = tx * 16;

    if (C1) {
        for (int idx = tid; idx < 540; idx += 256) {
            int c = idx / 180, p = idx - c * 180;
            int ry = p / 20, rx = p - ry * 20;
            int gx = x0 + rx;
            float v = 0.f;
            if (gx < IH) v = src[((b * 3 + c) * IH + (y0 + ry)) * IH + gx];
            xs[c * 180 + p] = v;
        }
        __syncthreads();
    }

    // prologue: stage B for tap 0 into buffer 0
    for (int idx = tid; idx < 1024; idx += 256)
        ((uint4*)(smem + C1_B))[idx] = ((const uint4*)Bplanes)[idx];

    // stage input (bn+relu), fp16 2-plane split into [px][cin] SW128 layout
    {
        int j = lane;
        int c0 = 2 * j, c1 = 2 * j + 1;
        float s0 = g_scale[lidx][c0], bb0 = g_bias[lidx][c0];
        float s1 = g_scale[lidx][c1], bb1 = g_bias[lidx][c1];
        float a00, a01, a02, a10, a11, a12;
        const float *sb0, *sb1;
        if (C1) {
            a00 = w0[c0 * 3]; a01 = w0[c0 * 3 + 1]; a02 = w0[c0 * 3 + 2];
            a10 = w0[c1 * 3]; a11 = w0[c1 * 3 + 1]; a12 = w0[c1 * 3 + 2];
        } else {
            sb0 = src + ((size_t)(b * 64 + c0)) * IH * IH;
            sb1 = src + ((size_t)(b * 64 + c1)) * IH * IH;
        }
        for (int p = mw; p < 180; p += 8) {
            float v0, v1;
            if (C1) {
                float xv0 = xs[p], xv1 = xs[180 + p], xv2 = xs[360 + p];
                v0 = xv0 * a00 + xv1 * a01 + xv2 * a02;
                v1 = xv0 * a10 + xv1 * a11 + xv2 * a12;
            } else {
                int ry = p / 20, rx = p - ry * 20;
                int gy = y0 + ry, gx = x0 + rx;
                v0 = 0.f; v1 = 0.f;
                if (gy < IH && gx < IH) {
                    v0 = sb0[gy * IH + gx];
                    v1 = sb1[gy * IH + gx];
                }
            }
            v0 = fmaxf(fmaf(v0, s0, bb0), 0.f);
            v1 = fmaxf(fmaf(v1, s1, bb1), 0.f);
            __half p0 = __float2half(v0);
            __half q0 = __float2half(v0 - __half2float(p0));
            __half p1 = __float2half(v1);
            __half q1 = __float2half(v1 - __half2float(p1));
            uint32_t off = SMEM_SWIZZLE_128B((uint32_t)(p * 128 + j * 4));
            *(uint32_t*)(smem + C1_H1 + off) =
                (uint32_t)__half_as_ushort(p0) |
                ((uint32_t)__half_as_ushort(p1) << 16);
            *(uint32_t*)(smem + C1_H2 + off) =
                (uint32_t)__half_as_ushort(q0) |
                ((uint32_t)__half_as_ushort(q1) << 16);
        }
    }
    __syncthreads();

    float acc[8][4];
#pragma unroll
    for (int j = 0; j < 8; j++)
#pragma unroll
        for (int q = 0; q < 4; q++) acc[j][q] = 0.f;

    for (int s = 0; s < 9; s++) {
        // stage B for tap s+1 into the other buffer (overlaps mma below)
        if (s + 1 < 9) {
            const uint4* gsrc = (const uint4*)(Bplanes + (s + 1) * 16384);
            uint4* sdst = (uint4*)(smem + C1_B + ((s + 1) & 1) * 16384);
            for (int idx = tid; idx < 1024; idx += 256) sdst[idx] = gsrc[idx];
        }

        const uint32_t b1_b = bB + (s & 1) * 16384;
        const uint32_t b2_b = b1_b + 8192;
        int ky = s / 3, kx = s - ky * 3;
        int m = mw * 16 + (lane & 15);
        int p = 0;
        if (m < 126) {
            int my = m / 18, mx = m - my * 18;
            p = (my + ky) * 20 + (mx + kx);
        }
        uint32_t arow = (uint32_t)(p * 128) + ((uint32_t)(lane >> 4) << 4);
#pragma unroll
        for (int kk = 0; kk < 4; kk++) {
            uint32_t a1[4], a2[4];
            uint32_t ao = SMEM_SWIZZLE_128B(arow + kk * 32);
            ldsm_x4(a1, h1_b + ao);
            ldsm_x4(a2, h2_b + ao);
            uint32_t brow = (uint32_t)((kk * 16 + (lane & 15)) * 128) +
                            ((uint32_t)(lane >> 4) << 4);
#pragma unroll
            for (int jp = 0; jp < 4; jp++) {
                uint32_t bb1[4], bb2[4];
                uint32_t bo = SMEM_SWIZZLE_128B(brow + jp * 32);
                ldsm_x4t(bb1, b1_b + bo);
                ldsm_x4t(bb2, b2_b + bo);
                mma_f16(acc[2 * jp], a1, bb1);
                mma_f16(acc[2 * jp], a1, bb2);
                mma_f16(acc[2 * jp], a2, bb1);
                mma_f16(acc[2 * jp + 1], a1, bb1 + 2);
                mma_f16(acc[2 * jp + 1], a1, bb2 + 2);
                mma_f16(acc[2 * jp + 1], a2, bb1 + 2);
            }
        }
        __syncthreads();  // tap s ldsm done + tap s+1 copy done
    }

    // epilogue: transpose through smem for coalesced global stores
    float* buf = (float*)smem;  // [128][65]
    int r0 = mw * 16 + (lane >> 2);
    int c0 = (lane & 3) * 2;
#pragma unroll
    for (int j = 0; j < 8; j++) {
        int oc = j * 8 + c0;
        buf[r0 * 65 + oc] = acc[j][0];
        buf[r0 * 65 + oc + 1] = acc[j][1];
        buf[(r0 + 8) * 65 + oc] = acc[j][2];
        buf[(r0 + 8) * 65 + oc + 1] = acc[j][3];
    }
    __syncthreads();
    for (int idx = tid; idx < 64 * 126; idx += 256) {
        int oc = idx / 126, m = idx - oc * 126;
        int my = m / 18, mx = m - my * 18;
        if (mx >= 16) continue;
        int oy = y0 + my, ox = x0 + mx;
        if (ox >= OH || oy >= OH) continue;
        dst[((size_t)(b * 64 + oc) * OH + oy) * OH + ox] = buf[m * 65 + oc];
    }
}

// ---------------------------------------------------------------------------
// fused maxpool(3,2) + per-channel stats; LAST BLOCK computes scale/bias.
template <int CH, int PH>
__global__ void poolstats_kernel(const float* __restrict__ src,
                                 float* __restrict__ dst, int l,
                                 const float* __restrict__ gamma,
                                 const float* __restrict__ beta, double N) {
    __shared__ float r1[256], r2[256];
    __shared__ bool is_last;
    int bc = blockIdx.x;
    int c = bc & 63;
    const float* sb = src + (size_t)bc * CH * CH;
    float* db = dst + (size_t)bc * PH * PH;
    float s = 0.f, q = 0.f;
    for (int i = threadIdx.x; i < PH * PH; i += 256) {
        int py = i / PH, px = i - py * PH;
        const float* w = sb + (2 * py) * CH + 2 * px;
        float m = w[0];
#pragma unroll
        for (int di = 0; di < 3; di++)
#pragma unroll
            for (int dj = 0; dj < 3; dj++) m = fmaxf(m, w[di * CH + dj]);
        db[i] = m;
        s += m;
        q = fmaf(m, m, q);
    }
    r1[threadIdx.x] = s; r2[threadIdx.x] = q;
    __syncthreads();
    for (int o = 128; o > 0; o >>= 1) {
        if (threadIdx.x < o) {
            r1[threadIdx.x] += r1[threadIdx.x + o];
            r2[threadIdx.x] += r2[threadIdx.x + o];
        }
        __syncthreads();
    }
    if (threadIdx.x == 0) {
        atomicAdd(&g_dsum[c], (double)r1[0]);
        atomicAdd(&g_dsq[c], (double)r2[0]);
    }
    __threadfence();
    if (threadIdx.x == 0)
        is_last = (atomicAdd(&g_cnt1, 1) == (int)gridDim.x - 1);
    __syncthreads();
    if (!is_last) return;
    __threadfence();
    int cc = threadIdx.x;
    if (cc < 64) {
        double m = g_dsum[cc] / N;
        double var = g_dsq[cc] / N - m * m;
        double sc = (double)gamma[cc] / sqrt(var + 1e-5);
        g_scale[l][cc] = (float)sc;
        g_bias[l][cc] = (float)((double)beta[cc] - m * sc);
    }
    __syncthreads();
    if (cc < 64) { g_dsum[cc] = 0.0; g_dsq[cc] = 0.0; }
    if (cc == 0) g_cnt1 = 0;
}

// ---------------------------------------------------------------------------
// FC; LAST BLOCK runs sequential spectral normalization.
__global__ void fc_kernel(const float* __restrict__ Wreg,
                          const float* __restrict__ breg,
                          const float* __restrict__ u0,
                          const float* __restrict__ v0) {
    __shared__ float red[256];
    __shared__ bool is_last;
    int j = blockIdx.x % 6, b = blockIdx.x / 6;
    const float* pb = g_p3 + (size_t)b * 10816;
    const float* wb = Wreg + (size_t)j * 10816;
    float s = 0.f;
    for (int k = threadIdx.x; k < 10816; k += 256) {
        int c = k / 169;
        float v = fmaxf(fmaf(pb[k], g_scale[3][c], g_bias[3][c]), 0.f);
        s += v * wb[k];
    }
    red[threadIdx.x] = s;
    __syncthreads();
    for (int o = 128; o > 0; o >>= 1) {
        if (threadIdx.x < o) red[threadIdx.x] += red[threadIdx.x + o];
        __syncthreads();
    }
    if (threadIdx.x == 0) g_traw[b * 6 + j] = red[0] + breg[j];
    __threadfence();
    if (threadIdx.x == 0)
        is_last = (atomicAdd(&g_cnt2, 1) == (int)gridDim.x - 1);
    __syncthreads();
    if (!is_last) return;
    if (threadIdx.x != 0) return;
    __threadfence();
    g_cnt2 = 0;
    float u[2] = {u0[0], u0[1]};
    float v[3] = {v0[0], v0[1], v0[2]};
    for (int bb = 0; bb < 32; bb++) {
        float W[6];
#pragma unroll
        for (int i = 0; i < 6; i++) W[i] = g_traw[bb * 6 + i];
#pragma unroll
        for (int it = 0; it < 4; it++) {
            float nv[3];
#pragma unroll
            for (int jj = 0; jj < 3; jj++)
                nv[jj] = W[jj] * u[0] + W[3 + jj] * u[1];
            float n = sqrtf(nv[0] * nv[0] + nv[1] * nv[1] + nv[2] * nv[2]);
            n = fmaxf(n, 1e-12f);
#pragma unroll
            for (int jj = 0; jj < 3; jj++) v[jj] = nv[jj] / n;
            float nu0 = W[0] * v[0] + W[1] * v[1] + W[2] * v[2];
            float nu1 = W[3] * v[0] + W[4] * v[1] + W[5] * v[2];
            n = sqrtf(nu0 * nu0 + nu1 * nu1);
            n = fmaxf(n, 1e-12f);
            u[0] = nu0 / n; u[1] = nu1 / n;
        }
        float Wv0 = W[0] * v[0] + W[1] * v[1] + W[2] * v[2];
        float Wv1 = W[3] * v[0] + W[4] * v[1] + W[5] * v[2];
        float sigma = u[0] * Wv0 + u[1] * Wv1;
#pragma unroll
        for (int i = 0; i < 6; i++) g_theta[bb * 6 + i] = W[i] / sigma;
    }
}

// affine grid + reflection bilinear sample
__global__ void sample_kernel(const float* __restrict__ x,
                              float* __restrict__ out) {
    int idx = blockIdx.x * 256 + threadIdx.x;
    if (idx >= BATCH * 16384) return;
    int b = idx >> 14, p = idx & 16383;
    int h = p >> 7, w = p & 127;
    const float* th = &g_theta[b * 6];
    float xsc = (2.f * w + 1.f) / 128.f - 1.f;
    float ysc = (2.f * h + 1.f) / 128.f - 1.f;
    float gx = th[0] * xsc + th[1] * ysc + th[2];
    float gy = th[3] * xsc + th[4] * ysc + th[5];
    float ix = ((gx + 1.f) * 128.f - 1.f) * 0.5f;
    float iy = ((gy + 1.f) * 128.f - 1.f) * 0.5f;
    float r = fmodf(fabsf(ix + 0.5f), 256.f);
    ix = (r > 128.f ? 256.f - r : r) - 0.5f;
    ix = fminf(fmaxf(ix, 0.f), 127.f);
    r = fmodf(fabsf(iy + 0.5f), 256.f);
    iy = (r > 128.f ? 256.f - r : r) - 0.5f;
    iy = fminf(fmaxf(iy, 0.f), 127.f);
    float fx0 = floorf(ix), fy0 = floorf(iy);
    float wx = ix - fx0, wy = iy - fy0;
    int x0 = min(max((int)fx0, 0), 127), y0 = min(max((int)fy0, 0), 127);
    int x1 = min(x0 + 1, 127), y1 = min(y0 + 1, 127);
    float w00 = (1.f - wx) * (1.f - wy), w10 = wx * (1.f - wy);
    float w01 = (1.f - wx) * wy, w11 = wx * wy;
#pragma unroll
    for (int c = 0; c < 3; c++) {
        const float* xb = x + (size_t)(b * 3 + c) * 16384;
        float v = xb[y0 * 128 + x0] * w00 + xb[y0 * 128 + x1] * w10 +
                  xb[y1 * 128 + x0] * w01 + xb[y1 * 128 + x1] * w11;
        out[(size_t)(b * 3 + c) * 16384 + p] = v;
    }
}

// ---------------------------------------------------------------------------
extern "C" void kernel_launch(void* const* d_in, const int* in_sizes, int n_in,
                              void* d_out, int out_size) {
    const float* x     = (const float*)d_in[0];
    const float* w0    = (const float*)d_in[1];
    const float* w1    = (const float*)d_in[2];
    const float* w2    = (const float*)d_in[3];
    const float* w3    = (const float*)d_in[4];
    const float* gamma = (const float*)d_in[5];
    const float* beta  = (const float*)d_in[6];
    const float* Wreg  = (const float*)d_in[7];
    const float* breg  = (const float*)d_in[8];
    const float* u0    = (const float*)d_in[9];
    const float* v0    = (const float*)d_in[10];
    float* out = (float*)d_out;
    (void)n_in; (void)in_sizes; (void)out_size;

    float *pa1, *pp1, *pa2, *pp2, *pa3, *pp3;
    char *pB1, *pB2, *pB3;
    cudaGetSymbolAddress((void**)&pa1, g_a1);
    cudaGetSymbolAddress((void**)&pp1, g_p1);
    cudaGetSymbolAddress((void**)&pa2, g_a2);
    cudaGetSymbolAddress((void**)&pp2, g_p2);
    cudaGetSymbolAddress((void**)&pa3, g_a3);
    cudaGetSymbolAddress((void**)&pp3, g_p3);
    cudaGetSymbolAddress((void**)&pB1, g_Bs1);
    cudaGetSymbolAddress((void**)&pB2, g_Bs2);
    cudaGetSymbolAddress((void**)&pB3, g_Bs3);

    cudaFuncSetAttribute(conv_mma_kernel<128, true>,
                         cudaFuncAttributeMaxDynamicSharedMemorySize, C1_SMEM);
    cudaFuncSetAttribute(conv_mma_kernel<62, false>,
                         cudaFuncAttributeMaxDynamicSharedMemorySize, C1_SMEM);
    cudaFuncSetAttribute(conv_mma_kernel<29, false>,
                         cudaFuncAttributeMaxDynamicSharedMemorySize, C1_SMEM);

    // weight pre-split + stats(x) + fused analytic BN0
    wsplit_kernel<<<dim3(9, 3), 256>>>(w1, w2, w3);
    statsx_kernel<<<512, 256>>>(x, w0, gamma, beta);

    // conv1 (HMMA fp16x2, fused conv0+bn0+relu) -> pool+stats+bn1
    conv_mma_kernel<128, true>
        <<<dim3(144, 32), 256, C1_SMEM>>>(x, w0, pB1, pa1, 0);
    poolstats_kernel<126, 62>
        <<<2048, 256>>>(pa1, pp1, 1, gamma + 64, beta + 64, 123008.0);

    // conv2 (HMMA fp16x2) -> pool+stats+bn2
    conv_mma_kernel<62, false>
        <<<dim3(36, 32), 256, C1_SMEM>>>(pp1, w0, pB2, pa2, 1);
    poolstats_kernel<60, 29>
        <<<2048, 256>>>(pa2, pp2, 2, gamma + 128, beta + 128, 26912.0);

    // conv3 (HMMA fp16x2) -> pool+stats+bn3
    conv_mma_kernel<29, false>
        <<<dim3(8, 32), 256, C1_SMEM>>>(pp2, w0, pB3, pa3, 2);
    poolstats_kernel<27, 13>
        <<<2048, 256>>>(pa3, pp3, 3, gamma + 192, beta + 192, 5408.0);

    // fc + fused spectral norm, then sampling
    fc_kernel<<<192, 256>>>(Wreg, breg, u0, v0);
    sample_kernel<<<(32 * 16384 + 255) / 256, 256>>>(x, out);
}

// round 17
// speedup vs baseline: 2.4120x; 1.0952x over previous
#include <cuda_runtime.h>
#include <cuda_fp16.h>
#include <math.h>
#include <stdint.h>

#define BATCH 32

// scratch (device globals: sanctioned workaround for no-alloc rule)
__device__ float g_a1[32 * 64 * 126 * 126];
__device__ float g_p1[32 * 64 * 62 * 62];
__device__ float g_a2[32 * 64 * 60 * 60];
__device__ float g_p2[32 * 64 * 29 * 29];
__device__ float g_a3[32 * 64 * 27 * 27];
__device__ float g_p3[32 * 64 * 13 * 13];
__device__ __align__(16) char g_Bs1[9][2][8192];  // pre-split swizzled w1
__device__ __align__(16) char g_Bs2[9][2][8192];  // pre-split swizzled w2
__device__ __align__(16) char g_Bs3[9][2][8192];  // pre-split swizzled w3
__device__ double g_dsum[64];
__device__ double g_dsq[64];
__device__ double g_xs[9];
__device__ float g_scale[4][64];
__device__ float g_bias[4][64];
__device__ float g_traw[32 * 6];
__device__ float g_theta[32 * 6];
__device__ int g_cnt0, g_cnt1, g_cnt2;

// ---------------------------------------------------------------------------
__device__ __forceinline__ uint32_t smem_to_u32(const void* p) {
    uint32_t a;
    asm("{ .reg .u64 t; cvta.to.shared.u64 t, %1; cvt.u32.u64 %0, t; }"
        : "=r"(a) : "l"(p));
    return a;
}
#define SMEM_SWIZZLE_128B(bo) ((bo) ^ (((bo) >> 3) & 0x70))

__device__ __forceinline__ void ldsm_x4(uint32_t* r, uint32_t addr) {
    asm volatile(
        "ldmatrix.sync.aligned.m8n8.x4.shared.b16 {%0,%1,%2,%3}, [%4];"
        : "=r"(r[0]), "=r"(r[1]), "=r"(r[2]), "=r"(r[3]) : "r"(addr));
}
__device__ __forceinline__ void ldsm_x4t(uint32_t* r, uint32_t addr) {
    asm volatile(
        "ldmatrix.sync.aligned.m8n8.x4.trans.shared.b16 {%0,%1,%2,%3}, [%4];"
        : "=r"(r[0]), "=r"(r[1]), "=r"(r[2]), "=r"(r[3]) : "r"(addr));
}
__device__ __forceinline__ void mma_f16(float* d, const uint32_t* a,
                                        const uint32_t* b) {
    asm volatile(
        "mma.sync.aligned.m16n8k16.row.col.f32.f16.f16.f32 "
        "{%0,%1,%2,%3}, {%4,%5,%6,%7}, {%8,%9}, {%0,%1,%2,%3};"
        : "+f"(d[0]), "+f"(d[1]), "+f"(d[2]), "+f"(d[3])
        : "r"(a[0]), "r"(a[1]), "r"(a[2]), "r"(a[3]), "r"(b[0]), "r"(b[1]));
}

// dynamic smem layout (bytes), sized for the 2x64 variant (SPX=264)
#define C1_XS 0        // float[3*264] = 3168
#define C1_H1 3200     // fp16 [SPX][64] SW128, 33792 max
#define C1_H2 36992
#define C1_B 70784     // [2 bufs][2 planes][8192] = 32768
#define C1_SMEM 103552

// ---------------------------------------------------------------------------
// pre-split w1/w2/w3 into 2 fp16 planes per tap, SW128-swizzled [cin][cout]
__global__ void wsplit_kernel(const float* __restrict__ w1,
                              const float* __restrict__ w2,
                              const float* __restrict__ w3) {
    int s = blockIdx.x;
    const float* w = (blockIdx.y == 0) ? w1 : (blockIdx.y == 1) ? w2 : w3;
    char (*Bs)[2][8192] =
        (blockIdx.y == 0) ? g_Bs1 : (blockIdx.y == 1) ? g_Bs2 : g_Bs3;
    for (int idx = threadIdx.x; idx < 4096; idx += 256) {
        int oc = idx >> 6, cin = idx & 63;
        float wv = w[(oc * 64 + cin) * 9 + s];
        __half w1h = __float2half(wv);
        __half w2h = __float2half(wv - __half2float(w1h));
        uint32_t off = SMEM_SWIZZLE_128B((uint32_t)(cin * 128 + oc * 2));
        *(__half*)(&Bs[s][0][off]) = w1h;
        *(__half*)(&Bs[s][1][off]) = w2h;
    }
}

// ---------------------------------------------------------------------------
// statsx: second moments of x via warp shuffles; LAST BLOCK computes BN0.
__global__ void statsx_kernel(const float* __restrict__ x,
                              const float* __restrict__ w0,
                              const float* __restrict__ gamma,
                              const float* __restrict__ beta) {
    __shared__ float wred[8][9];
    __shared__ bool is_last;
    float a[9];
#pragma unroll
    for (int i = 0; i < 9; i++) a[i] = 0.f;
    for (int idx = blockIdx.x * 256 + threadIdx.x; idx < BATCH * 16384;
         idx += gridDim.x * 256) {
        int b = idx >> 14, p = idx & 16383;
        float x0 = x[(b * 3 + 0) * 16384 + p];
        float x1 = x[(b * 3 + 1) * 16384 + p];
        float x2 = x[(b * 3 + 2) * 16384 + p];
        a[0] = fmaf(x0, x0, a[0]); a[1] = fmaf(x0, x1, a[1]);
        a[2] = fmaf(x0, x2, a[2]); a[3] = fmaf(x1, x1, a[3]);
        a[4] = fmaf(x1, x2, a[4]); a[5] = fmaf(x2, x2, a[5]);
        a[6] += x0; a[7] += x1; a[8] += x2;
    }
    int lane = threadIdx.x & 31, wid = threadIdx.x >> 5;
#pragma unroll
    for (int q = 0; q < 9; q++) {
#pragma unroll
        for (int o = 16; o > 0; o >>= 1)
            a[q] += __shfl_xor_sync(0xffffffffu, a[q], o);
        if (lane == 0) wred[wid][q] = a[q];
    }
    __syncthreads();
    if (threadIdx.x < 9) {
        float s = 0.f;
#pragma unroll
        for (int w = 0; w < 8; w++) s += wred[w][threadIdx.x];
        atomicAdd(&g_xs[threadIdx.x], (double)s);
    }
    __threadfence();
    if (threadIdx.x == 0)
        is_last = (atomicAdd(&g_cnt0, 1) == (int)gridDim.x - 1);
    __syncthreads();
    if (!is_last) return;
    __threadfence();
    int o = threadIdx.x;
    if (o < 64) {
        const double N = 524288.0;
        double C00 = g_xs[0] / N, C01 = g_xs[1] / N, C02 = g_xs[2] / N;
        double C11 = g_xs[3] / N, C12 = g_xs[4] / N, C22 = g_xs[5] / N;
        double m0 = g_xs[6] / N, m1 = g_xs[7] / N, m2 = g_xs[8] / N;
        double w0v = w0[o * 3 + 0], w1v = w0[o * 3 + 1], w2v = w0[o * 3 + 2];
        double m = w0v * m0 + w1v * m1 + w2v * m2;
        double e2 = w0v * w0v * C00 + w1v * w1v * C11 + w2v * w2v * C22 +
                    2.0 * (w0v * w1v * C01 + w0v * w2v * C02 + w1v * w2v * C12);
        double var = e2 - m * m;
        double sc = (double)gamma[o] / sqrt(var + 1e-5);
        g_scale[0][o] = (float)sc;
        g_bias[0][o] = (float)((double)beta[o] - m * sc);
    }
    __syncthreads();
    if (threadIdx.x < 9) g_xs[threadIdx.x] = 0.0;
    if (threadIdx.x == 0) g_cnt0 = 0;
}

// ---------------------------------------------------------------------------
// conv via mma.sync, fp16 2-plane split (3 products), 9 taps, implicit GEMM.
// Tile: RR rows x CC cols = 128 M-rows (2x64 or 7x16-span), N=64 couts.
// B planes double-buffered (copy tap s+1 during tap s mma).
template <int IH, int RR, int CC, bool C1>
__global__ __launch_bounds__(256, 2) void conv_mma_kernel(
    const float* __restrict__ src, const float* __restrict__ w0,
    const char* __restrict__ Bplanes, float* __restrict__ dst, int lidx) {
    constexpr int OH = IH - 2;
    constexpr int TXn = (OH + CC - 1) / CC;
    constexpr int PITCH = (CC == 64) ? 66 : 20;
    constexpr int SPAN = (CC == 64) ? 66 : 18;
    constexpr int SPX = (RR + 2) * PITCH;
    extern __shared__ char smem[];
    float* xs = (float*)(smem + C1_XS);
    const uint32_t h1_b = smem_to_u32(smem + C1_H1);
    const uint32_t h2_b = smem_to_u32(smem + C1_H2);
    const uint32_t bB = smem_to_u32(smem + C1_B);
    const int tid = threadIdx.x;
    const int lane = tid & 31, mw = tid >> 5;
    const int b = blockIdx.y;
    const int tx = blockIdx.x % TXn, ty = blockIdx.x / TXn;
    const int y0 = ty * RR, x0 = tx * CC;

    // prologue: stage B for tap 0 into buffer 0
    for (int idx = tid; idx < 1024; idx += 256)
        ((uint4*)(smem + C1_B))[idx] = ((const uint4*)Bplanes)[idx];

    if (C1) {
        for (int idx = tid; idx < 3 * SPX; idx += 256) {
            int c = idx / SPX, p = idx - c * SPX;
            int ry = p / PITCH, rx = p - ry * PITCH;
            int gy = y0 + ry, gx = x0 + rx;
            float v = 0.f;
            if (gy < IH && gx < IH) v = src[((b * 3 + c) * IH + gy) * IH + gx];
            xs[c * SPX + p] = v;
        }
        __syncthreads();
        // conv0+bn0+relu, fp16 2-plane split into [px][cin] SW128 layout
        int j = lane;
        int c0 = 2 * j, c1 = 2 * j + 1;
        float s0 = g_scale[0][c0], bb0 = g_bias[0][c0];
        float s1 = g_scale[0][c1], bb1 = g_bias[0][c1];
        float a00 = w0[c0 * 3], a01 = w0[c0 * 3 + 1], a02 = w0[c0 * 3 + 2];
        float a10 = w0[c1 * 3], a11 = w0[c1 * 3 + 1], a12 = w0[c1 * 3 + 2];
        for (int p = mw; p < SPX; p += 8) {
            float xv0 = xs[p], xv1 = xs[SPX + p], xv2 = xs[2 * SPX + p];
            float v0 = fmaxf(fmaf(xv0 * a00 + xv1 * a01 + xv2 * a02, s0, bb0),
                             0.f);
            float v1 = fmaxf(fmaf(xv0 * a10 + xv1 * a11 + xv2 * a12, s1, bb1),
                             0.f);
            __half p0 = __float2half(v0);
            __half q0 = __float2half(v0 - __half2float(p0));
            __half p1 = __float2half(v1);
            __half q1 = __float2half(v1 - __half2float(p1));
            uint32_t off = SMEM_SWIZZLE_128B((uint32_t)(p * 128 + j * 4));
            *(uint32_t*)(smem + C1_H1 + off) =
                (uint32_t)__half_as_ushort(p0) |
                ((uint32_t)__half_as_ushort(p1) << 16);
            *(uint32_t*)(smem + C1_H2 + off) =
                (uint32_t)__half_as_ushort(q0) |
                ((uint32_t)__half_as_ushort(q1) << 16);
        }
    } else {
        // coalesced p-major staging: lane sweeps px of one channel
        for (int idx = tid; idx < 64 * SPX; idx += 256) {
            int c = idx / SPX, p = idx - c * SPX;
            int ry = p / PITCH, rx = p - ry * PITCH;
            int gy = y0 + ry, gx = x0 + rx;
            float v = 0.f;
            if (gy < IH && gx < IH)
                v = src[((size_t)(b * 64 + c)) * IH * IH + gy * IH + gx];
            v = fmaxf(fmaf(v, g_scale[lidx][c], g_bias[lidx][c]), 0.f);
            __half p0 = __float2half(v);
            __half q0 = __float2half(v - __half2float(p0));
            uint32_t off = SMEM_SWIZZLE_128B((uint32_t)(p * 128 + c * 2));
            *(__half*)(smem + C1_H1 + off) = p0;
            *(__half*)(smem + C1_H2 + off) = q0;
        }
    }
    __syncthreads();

    float acc[8][4];
#pragma unroll
    for (int j = 0; j < 8; j++)
#pragma unroll
        for (int q = 0; q < 4; q++) acc[j][q] = 0.f;

    for (int s = 0; s < 9; s++) {
        // stage B for tap s+1 into the other buffer (overlaps mma below)
        if (s + 1 < 9) {
            const uint4* gsrc = (const uint4*)(Bplanes + (s + 1) * 16384);
            uint4* sdst = (uint4*)(smem + C1_B + ((s + 1) & 1) * 16384);
            for (int idx = tid; idx < 1024; idx += 256) sdst[idx] = gsrc[idx];
        }

        const uint32_t b1_b = bB + (s & 1) * 16384;
        const uint32_t b2_b = b1_b + 8192;
        int ky = s / 3, kx = s - ky * 3;
        int m = mw * 16 + (lane & 15);
        int p;
        if (CC == 64) {
            int my = m >> 6, mx = m & 63;
            p = (my + ky) * PITCH + (mx + kx);
        } else {
            p = 0;
            if (m < RR * SPAN) {
                int my = m / SPAN, mx = m - my * SPAN;
                p = (my + ky) * PITCH + (mx + kx);
            }
        }
        uint32_t arow = (uint32_t)(p * 128) + ((uint32_t)(lane >> 4) << 4);
#pragma unroll
        for (int kk = 0; kk < 4; kk++) {
            uint32_t a1[4], a2[4];
            uint32_t ao = SMEM_SWIZZLE_128B(arow + kk * 32);
            ldsm_x4(a1, h1_b + ao);
            ldsm_x4(a2, h2_b + ao);
            uint32_t brow = (uint32_t)((kk * 16 + (lane & 15)) * 128) +
                            ((uint32_t)(lane >> 4) << 4);
#pragma unroll
            for (int jp = 0; jp < 4; jp++) {
                uint32_t bb1[4], bb2[4];
                uint32_t bo = SMEM_SWIZZLE_128B(brow + jp * 32);
                ldsm_x4t(bb1, b1_b + bo);
                ldsm_x4t(bb2, b2_b + bo);
                mma_f16(acc[2 * jp], a1, bb1);
                mma_f16(acc[2 * jp], a1, bb2);
                mma_f16(acc[2 * jp], a2, bb1);
                mma_f16(acc[2 * jp + 1], a1, bb1 + 2);
                mma_f16(acc[2 * jp + 1], a1, bb2 + 2);
                mma_f16(acc[2 * jp + 1], a2, bb1 + 2);
            }
        }
        __syncthreads();  // tap s ldsm done + tap s+1 copy done
    }

    // epilogue: transpose through smem for coalesced global stores
    float* buf = (float*)smem;  // [128][65]
    int r0 = mw * 16 + (lane >> 2);
    int c0 = (lane & 3) * 2;
#pragma unroll
    for (int j = 0; j < 8; j++) {
        int oc = j * 8 + c0;
        buf[r0 * 65 + oc] = acc[j][0];
        buf[r0 * 65 + oc + 1] = acc[j][1];
        buf[(r0 + 8) * 65 + oc] = acc[j][2];
        buf[(r0 + 8) * 65 + oc + 1] = acc[j][3];
    }
    __syncthreads();
    if (CC == 64) {
        for (int idx = tid; idx < 64 * 128; idx += 256) {
            int oc = idx >> 7, m = idx & 127;
            int my = m >> 6, mx = m & 63;
            int oy = y0 + my, ox = x0 + mx;
            if (oy >= OH || ox >= OH) continue;
            dst[((size_t)(b * 64 + oc) * OH + oy) * OH + ox] =
                buf[m * 65 + oc];
        }
    } else {
        for (int idx = tid; idx < 64 * RR * SPAN; idx += 256) {
            int oc = idx / (RR * SPAN), m = idx - oc * (RR * SPAN);
            int my = m / SPAN, mx = m - my * SPAN;
            if (mx >= CC) continue;
            int oy = y0 + my, ox = x0 + mx;
            if (ox >= OH || oy >= OH) continue;
            dst[((size_t)(b * 64 + oc) * OH + oy) * OH + ox] =
                buf[m * 65 + oc];
        }
    }
}

// ---------------------------------------------------------------------------
// fused maxpool(3,2) + per-channel stats; LAST BLOCK computes scale/bias.
template <int CH, int PH>
__global__ void poolstats_kernel(const float* __restrict__ src,
                                 float* __restrict__ dst, int l,
                                 const float* __restrict__ gamma,
                                 const float* __restrict__ beta, double N) {
    __shared__ float r1[256], r2[256];
    __shared__ bool is_last;
    int bc = blockIdx.x;
    int c = bc & 63;
    const float* sb = src + (size_t)bc * CH * CH;
    float* db = dst + (size_t)bc * PH * PH;
    float s = 0.f, q = 0.f;
    for (int i = threadIdx.x; i < PH * PH; i += 256) {
        int py = i / PH, px = i - py * PH;
        const float* w = sb + (2 * py) * CH + 2 * px;
        float m = w[0];
#pragma unroll
        for (int di = 0; di < 3; di++)
#pragma unroll
            for (int dj = 0; dj < 3; dj++) m = fmaxf(m, w[di * CH + dj]);
        db[i] = m;
        s += m;
        q = fmaf(m, m, q);
    }
    r1[threadIdx.x] = s; r2[threadIdx.x] = q;
    __syncthreads();
    for (int o = 128; o > 0; o >>= 1) {
        if (threadIdx.x < o) {
            r1[threadIdx.x] += r1[threadIdx.x + o];
            r2[threadIdx.x] += r2[threadIdx.x + o];
        }
        __syncthreads();
    }
    if (threadIdx.x == 0) {
        atomicAdd(&g_dsum[c], (double)r1[0]);
        atomicAdd(&g_dsq[c], (double)r2[0]);
    }
    __threadfence();
    if (threadIdx.x == 0)
        is_last = (atomicAdd(&g_cnt1, 1) == (int)gridDim.x - 1);
    __syncthreads();
    if (!is_last) return;
    __threadfence();
    int cc = threadIdx.x;
    if (cc < 64) {
        double m = g_dsum[cc] / N;
        double var = g_dsq[cc] / N - m * m;
        double sc = (double)gamma[cc] / sqrt(var + 1e-5);
        g_scale[l][cc] = (float)sc;
        g_bias[l][cc] = (float)((double)beta[cc] - m * sc);
    }
    __syncthreads();
    if (cc < 64) { g_dsum[cc] = 0.0; g_dsq[cc] = 0.0; }
    if (cc == 0) g_cnt1 = 0;
}

// ---------------------------------------------------------------------------
// FC; LAST BLOCK runs sequential spectral normalization.
__global__ void fc_kernel(const float* __restrict__ Wreg,
                          const float* __restrict__ breg,
                          const float* __restrict__ u0,
                          const float* __restrict__ v0) {
    __shared__ float red[256];
    __shared__ bool is_last;
    int j = blockIdx.x % 6, b = blockIdx.x / 6;
    const float* pb = g_p3 + (size_t)b * 10816;
    const float* wb = Wreg + (size_t)j * 10816;
    float s = 0.f;
    for (int k = threadIdx.x; k < 10816; k += 256) {
        int c = k / 169;
        float v = fmaxf(fmaf(pb[k], g_scale[3][c], g_bias[3][c]), 0.f);
        s += v * wb[k];
    }
    red[threadIdx.x] = s;
    __syncthreads();
    for (int o = 128; o > 0; o >>= 1) {
        if (threadIdx.x < o) red[threadIdx.x] += red[threadIdx.x + o];
        __syncthreads();
    }
    if (threadIdx.x == 0) g_traw[b * 6 + j] = red[0] + breg[j];
    __threadfence();
    if (threadIdx.x == 0)
        is_last = (atomicAdd(&g_cnt2, 1) == (int)gridDim.x - 1);
    __syncthreads();
    if (!is_last) return;
    if (threadIdx.x != 0) return;
    __threadfence();
    g_cnt2 = 0;
    float u[2] = {u0[0], u0[1]};
    float v[3] = {v0[0], v0[1], v0[2]};
    for (int bb = 0; bb < 32; bb++) {
        float W[6];
#pragma unroll
        for (int i = 0; i < 6; i++) W[i] = g_traw[bb * 6 + i];
#pragma unroll
        for (int it = 0; it < 4; it++) {
            float nv[3];
#pragma unroll
            for (int jj = 0; jj < 3; jj++)
                nv[jj] = W[jj] * u[0] + W[3 + jj] * u[1];
            float n = sqrtf(nv[0] * nv[0] + nv[1] * nv[1] + nv[2] * nv[2]);
            n = fmaxf(n, 1e-12f);
#pragma unroll
            for (int jj = 0; jj < 3; jj++) v[jj] = nv[jj] / n;
            float nu0 = W[0] * v[0] + W[1] * v[1] + W[2] * v[2];
            float nu1 = W[3] * v[0] + W[4] * v[1] + W[5] * v[2];
            n = sqrtf(nu0 * nu0 + nu1 * nu1);
            n = fmaxf(n, 1e-12f);
            u[0] = nu0 / n; u[1] = nu1 / n;
        }
        float Wv0 = W[0] * v[0] + W[1] * v[1] + W[2] * v[2];
        float Wv1 = W[3] * v[0] + W[4] * v[1] + W[5] * v[2];
        float sigma = u[0] * Wv0 + u[1] * Wv1;
#pragma unroll
        for (int i = 0; i < 6; i++) g_theta[bb * 6 + i] = W[i] / sigma;
    }
}

// affine grid + reflection bilinear sample
__global__ void sample_kernel(const float* __restrict__ x,
                              float* __restrict__ out) {
    int idx = blockIdx.x * 256 + threadIdx.x;
    if (idx >= BATCH * 16384) return;
    int b = idx >> 14, p = idx & 16383;
    int h = p >> 7, w = p & 127;
    const float* th = &g_theta[b * 6];
    float xsc = (2.f * w + 1.f) / 128.f - 1.f;
    float ysc = (2.f * h + 1.f) / 128.f - 1.f;
    float gx = th[0] * xsc + th[1] * ysc + th[2];
    float gy = th[3] * xsc + th[4] * ysc + th[5];
    float ix = ((gx + 1.f) * 128.f - 1.f) * 0.5f;
    float iy = ((gy + 1.f) * 128.f - 1.f) * 0.5f;
    float r = fmodf(fabsf(ix + 0.5f), 256.f);
    ix = (r > 128.f ? 256.f - r : r) - 0.5f;
    ix = fminf(fmaxf(ix, 0.f), 127.f);
    r = fmodf(fabsf(iy + 0.5f), 256.f);
    iy = (r > 128.f ? 256.f - r : r) - 0.5f;
    iy = fminf(fmaxf(iy, 0.f), 127.f);
    float fx0 = floorf(ix), fy0 = floorf(iy);
    float wx = ix - fx0, wy = iy - fy0;
    int x0 = min(max((int)fx0, 0), 127), y0 = min(max((int)fy0, 0), 127);
    int x1 = min(x0 + 1, 127), y1 = min(y0 + 1, 127);
    float w00 = (1.f - wx) * (1.f - wy), w10 = wx * (1.f - wy);
    float w01 = (1.f - wx) * wy, w11 = wx * wy;
#pragma unroll
    for (int c = 0; c < 3; c++) {
        const float* xb = x + (size_t)(b * 3 + c) * 16384;
        float v = xb[y0 * 128 + x0] * w00 + xb[y0 * 128 + x1] * w10 +
                  xb[y1 * 128 + x0] * w01 + xb[y1 * 128 + x1] * w11;
        out[(size_t)(b * 3 + c) * 16384 + p] = v;
    }
}

// ---------------------------------------------------------------------------
extern "C" void kernel_launch(void* const* d_in, const int* in_sizes, int n_in,
                              void* d_out, int out_size) {
    const float* x     = (const float*)d_in[0];
    const float* w0    = (const float*)d_in[1];
    const float* w1    = (const float*)d_in[2];
    const float* w2    = (const float*)d_in[3];
    const float* w3    = (const float*)d_in[4];
    const float* gamma = (const float*)d_in[5];
    const float* beta  = (const float*)d_in[6];
    const float* Wreg  = (const float*)d_in[7];
    const float* breg  = (const float*)d_in[8];
    const float* u0    = (const float*)d_in[9];
    const float* v0    = (const float*)d_in[10];
    float* out = (float*)d_out;
    (void)n_in; (void)in_sizes; (void)out_size;

    float *pa1, *pp1, *pa2, *pp2, *pa3, *pp3;
    char *pB1, *pB2, *pB3;
    cudaGetSymbolAddress((void**)&pa1, g_a1);
    cudaGetSymbolAddress((void**)&pp1, g_p1);
    cudaGetSymbolAddress((void**)&pa2, g_a2);
    cudaGetSymbolAddress((void**)&pp2, g_p2);
    cudaGetSymbolAddress((void**)&pa3, g_a3);
    cudaGetSymbolAddress((void**)&pp3, g_p3);
    cudaGetSymbolAddress((void**)&pB1, g_Bs1);
    cudaGetSymbolAddress((void**)&pB2, g_Bs2);
    cudaGetSymbolAddress((void**)&pB3, g_Bs3);

    cudaFuncSetAttribute(conv_mma_kernel<128, 2, 64, true>,
                         cudaFuncAttributeMaxDynamicSharedMemorySize, C1_SMEM);
    cudaFuncSetAttribute(conv_mma_kernel<62, 2, 64, false>,
                         cudaFuncAttributeMaxDynamicSharedMemorySize, C1_SMEM);
    cudaFuncSetAttribute(conv_mma_kernel<29, 7, 16, false>,
                         cudaFuncAttributeMaxDynamicSharedMemorySize, C1_SMEM);

    // weight pre-split + stats(x) + fused analytic BN0
    wsplit_kernel<<<dim3(9, 3), 256>>>(w1, w2, w3);
    statsx_kernel<<<512, 256>>>(x, w0, gamma, beta);

    // conv1 (HMMA fp16x2, fused conv0+bn0+relu, 2x64 tiles) -> pool+stats+bn1
    conv_mma_kernel<128, 2, 64, true>
        <<<dim3(126, 32), 256, C1_SMEM>>>(x, w0, pB1, pa1, 0);
    poolstats_kernel<126, 62>
        <<<2048, 256>>>(pa1, pp1, 1, gamma + 64, beta + 64, 123008.0);

    // conv2 (HMMA fp16x2, 2x64 tiles) -> pool+stats+bn2
    conv_mma_kernel<62, 2, 64, false>
        <<<dim3(30, 32), 256, C1_SMEM>>>(pp1, w0, pB2, pa2, 1);
    poolstats_kernel<60, 29>
        <<<2048, 256>>>(pa2, pp2, 2, gamma + 128, beta + 128, 26912.0);

    // conv3 (HMMA fp16x2, 7x16 tiles) -> pool+stats+bn3
    conv_mma_kernel<29, 7, 16, false>
        <<<dim3(8, 32), 256, C1_SMEM>>>(pp2, w0, pB3, pa3, 2);
    poolstats_kernel<27, 13>
        <<<2048, 256>>>(pa3, pp3, 3, gamma + 192, beta + 192, 5408.0);

    // fc + fused spectral norm, then sampling
    fc_kernel<<<192, 256>>>(Wreg, breg, u0, v0);
    sample_kernel<<<(32 * 16384 + 255) / 256, 256>>>(x, out);
}